// round 1
// baseline (speedup 1.0000x reference)
#include <cuda_runtime.h>

// ---------------------------------------------------------------------------
// FCOS head: 3 FPN levels, N=8, C=256, GN(16 groups), towers + small heads.
// Round 1: correctness + solid fp32 CUDA-core implicit-GEMM conv.
// ---------------------------------------------------------------------------

#define ICB 8      // input channels per smem chunk
#define TH  8      // tile rows
#define TWC 32     // tile cols (all level widths are multiples of 32)

#define NPIX 16800                 // pixels per batch across all levels
#define REG_BASE 2688000L          // 8*16800*20
#define CTR_BASE 3225600L          // REG_BASE + 8*67200

// Scratch (static device memory: allowed; no cudaMalloc anywhere)
__device__ float g_A[26214400];    // 8*256*100*128
__device__ float g_B[26214400];
__device__ float g_mean[128];      // 8 batches * 16 groups
__device__ float g_rstd[128];

// ---------------------------------------------------------------------------
// conv3x3, stride 1, pad 1. Tile: OCT=8*OCR output channels x (8x32) pixels.
// 256 threads: oc_t = tid&7 (8 oc lanes), px_t = tid>>3 (32 px lanes, 8 px each).
// Per-thread oc are strided (oc_t + 8*i) so weight smem reads are conflict-free.
// MODE 0: plain NCHW store to scratch (tower convs)
// MODE 1: cls head -> out[( n*16800 + off + y*W + x )*20 + oc]
// MODE 2: reg(4ch,ReLU) + ctr(1ch) head -> reg/ctr regions of out
// ---------------------------------------------------------------------------
template<int OCR, int MODE>
__global__ __launch_bounds__(256, 2)
void conv3x3_k(const float* __restrict__ in, const float* __restrict__ w,
               const float* __restrict__ w2,
               const float* __restrict__ bias, const float* __restrict__ bias2,
               float* __restrict__ out,
               int C, int OC, int H, int W, int oc_tiles, int lvlOff)
{
    constexpr int OCT = 8 * OCR;
    __shared__ float sIn[ICB][TH + 2][TWC + 2];
    __shared__ float sW[ICB * 9][OCT];

    const int tid  = threadIdx.x;
    const int oc_t = tid & 7;
    const int px_t = tid >> 3;
    const int r    = px_t >> 2;          // row within tile (0..7)
    const int c0   = (px_t & 3) * 8;     // col group start (0,8,16,24)

    const int n  = blockIdx.z / oc_tiles;
    const int ot = blockIdx.z % oc_tiles;
    const int y0 = blockIdx.y * TH;
    const int x0 = blockIdx.x * TWC;
    const int ocBase = ot * OCT;

    float acc[OCR][8];
#pragma unroll
    for (int i = 0; i < OCR; ++i)
#pragma unroll
        for (int j = 0; j < 8; ++j) acc[i][j] = 0.f;

    const float* __restrict__ inN = in + (long)n * C * H * W;

    for (int ic0 = 0; ic0 < C; ic0 += ICB) {
        __syncthreads();
        // ---- stage input halo tile: ICB x (TH+2) x (TWC+2) ----
        for (int idx = tid; idx < ICB * (TH + 2) * (TWC + 2); idx += 256) {
            int ic  = idx / ((TH + 2) * (TWC + 2));
            int rem = idx % ((TH + 2) * (TWC + 2));
            int ly = rem / (TWC + 2);
            int lx = rem % (TWC + 2);
            int gy = y0 + ly - 1;
            int gx = x0 + lx - 1;
            float v = 0.f;
            if (gy >= 0 && gy < H && gx >= 0 && gx < W)
                v = inN[(long)(ic0 + ic) * H * W + (long)gy * W + gx];
            sIn[ic][ly][lx] = v;
        }
        // ---- stage weights: [ic*9+k][oc_local] ----
        for (int idx = tid; idx < ICB * 9 * OCT; idx += 256) {
            int oc  = idx / (ICB * 9);
            int rem = idx % (ICB * 9);        // ic*9 + k, contiguous in global
            int ocg = ocBase + oc;
            float v = 0.f;
            if (MODE == 2) {
                if (ocg < 4)       v = w [(long)ocg * C * 9 + ic0 * 9 + rem];
                else if (ocg == 4) v = w2[(long)ic0 * 9 + rem];
            } else {
                if (ocg < OC)      v = w [(long)ocg * C * 9 + ic0 * 9 + rem];
            }
            sW[rem][oc] = v;
        }
        __syncthreads();

#pragma unroll 1
        for (int ic = 0; ic < ICB; ++ic) {
#pragma unroll
            for (int ky = 0; ky < 3; ++ky)
#pragma unroll
            for (int kx = 0; kx < 3; ++kx) {
                float a[8];
#pragma unroll
                for (int j = 0; j < 8; ++j) a[j] = sIn[ic][r + ky][c0 + kx + j];
#pragma unroll
                for (int i = 0; i < OCR; ++i) {
                    float wv = sW[ic * 9 + ky * 3 + kx][oc_t + 8 * i];
#pragma unroll
                    for (int j = 0; j < 8; ++j)
                        acc[i][j] = fmaf(wv, a[j], acc[i][j]);
                }
            }
        }
    }

    const int y = y0 + r;
    if (y >= H) return;   // x always in-bounds: W is a multiple of 32

#pragma unroll
    for (int i = 0; i < OCR; ++i) {
        const int ocl = oc_t + 8 * i;
        const int oc  = ocBase + ocl;
        if (MODE == 0) {
            if (oc < OC) {
                float bv = bias[oc];
                float* op = out + ((long)(n * OC + oc) * H + y) * W + x0 + c0;
#pragma unroll
                for (int j = 0; j < 8; ++j) op[j] = acc[i][j] + bv;
            }
        } else if (MODE == 1) {
            if (oc < OC) {
                float bv = bias[oc];
                long pbase = ((long)n * NPIX + lvlOff + (long)y * W + x0 + c0) * 20 + oc;
#pragma unroll
                for (int j = 0; j < 8; ++j) out[pbase + (long)j * 20] = acc[i][j] + bv;
            }
        } else {  // MODE 2
            if (oc < 4) {
                float bv = bias[oc];
                long pbase = REG_BASE + (long)n * 67200
                           + ((long)(lvlOff + y * W + x0 + c0)) * 4 + oc;
#pragma unroll
                for (int j = 0; j < 8; ++j)
                    out[pbase + (long)j * 4] = fmaxf(acc[i][j] + bv, 0.f);
            } else if (oc == 4) {
                float bv = bias2[0];
                long pbase = CTR_BASE + (long)n * NPIX + lvlOff + (long)y * W + x0 + c0;
#pragma unroll
                for (int j = 0; j < 8; ++j) out[pbase + j] = acc[i][j] + bv;
            }
        }
    }
}

// ---------------------------------------------------------------------------
// GroupNorm stats: one block per (n, group). Channels of a group are
// contiguous in NCHW, so each block reduces a contiguous 16*HW span.
// Deterministic (no atomics).
// ---------------------------------------------------------------------------
__global__ void gn_stats_k(const float* __restrict__ x, int HW)
{
    const int n = blockIdx.x >> 4;
    const int g = blockIdx.x & 15;
    const float4* p = (const float4*)(x + ((long)n * 256 + (long)g * 16) * HW);
    const int total4 = (16 * HW) >> 2;

    float s = 0.f, s2 = 0.f;
    for (int i = threadIdx.x; i < total4; i += blockDim.x) {
        float4 v = p[i];
        s  += v.x + v.y + v.z + v.w;
        s2 += v.x * v.x + v.y * v.y + v.z * v.z + v.w * v.w;
    }
    __shared__ float rs[8], rs2[8];
#pragma unroll
    for (int o = 16; o; o >>= 1) {
        s  += __shfl_xor_sync(~0u, s, o);
        s2 += __shfl_xor_sync(~0u, s2, o);
    }
    const int wid = threadIdx.x >> 5, lid = threadIdx.x & 31;
    if (lid == 0) { rs[wid] = s; rs2[wid] = s2; }
    __syncthreads();
    if (wid == 0) {
        s  = (lid < 8) ? rs[lid]  : 0.f;
        s2 = (lid < 8) ? rs2[lid] : 0.f;
#pragma unroll
        for (int o = 4; o; o >>= 1) {
            s  += __shfl_xor_sync(~0u, s, o);
            s2 += __shfl_xor_sync(~0u, s2, o);
        }
        if (lid == 0) {
            float inv = 1.f / (float)(16 * HW);
            float m = s * inv;
            float var = s2 * inv - m * m;
            g_mean[blockIdx.x] = m;
            g_rstd[blockIdx.x] = rsqrtf(var + 1e-5f);
        }
    }
}

// GN apply + ReLU, float4 vectorized (HW is a multiple of 4)
__global__ void gn_apply_k(const float* __restrict__ x,
                           const float* __restrict__ gamma,
                           const float* __restrict__ beta,
                           float* __restrict__ y, int HW)
{
    long idx = (long)blockIdx.x * blockDim.x + threadIdx.x;   // float4 units
    long total4 = (long)8 * 256 * HW / 4;
    if (idx >= total4) return;
    long nc = (idx * 4) / HW;
    int n = (int)(nc >> 8), c = (int)(nc & 255);
    int sg = (n << 4) + (c >> 4);
    float m  = g_mean[sg];
    float rsd = g_rstd[sg];
    float sc = rsd * gamma[c];
    float sh = beta[c] - m * sc;
    float4 v = ((const float4*)x)[idx];
    v.x = fmaxf(v.x * sc + sh, 0.f);
    v.y = fmaxf(v.y * sc + sh, 0.f);
    v.z = fmaxf(v.z * sc + sh, 0.f);
    v.w = fmaxf(v.w * sc + sh, 0.f);
    ((float4*)y)[idx] = v;
}

// ---------------------------------------------------------------------------
extern "C" void kernel_launch(void* const* d_in, const int* in_sizes, int n_in,
                              void* d_out, int out_size)
{
    (void)in_sizes; (void)n_in; (void)out_size;
    const float* feat[3]     = { (const float*)d_in[0], (const float*)d_in[1], (const float*)d_in[2] };
    const float* cls_conv_w  = (const float*)d_in[3];
    const float* cls_conv_b  = (const float*)d_in[4];
    const float* cls_gn_g    = (const float*)d_in[5];
    const float* cls_gn_b    = (const float*)d_in[6];
    const float* cls_out_w   = (const float*)d_in[7];
    const float* cls_out_b   = (const float*)d_in[8];
    const float* reg_conv_w  = (const float*)d_in[9];
    const float* reg_conv_b  = (const float*)d_in[10];
    const float* reg_gn_g    = (const float*)d_in[11];
    const float* reg_gn_b    = (const float*)d_in[12];
    const float* reg_out_w   = (const float*)d_in[13];
    const float* reg_out_b   = (const float*)d_in[14];
    const float* ctr_w       = (const float*)d_in[15];
    const float* ctr_b       = (const float*)d_in[16];
    float* out = (float*)d_out;

    float *pA = nullptr, *pB = nullptr;
    cudaGetSymbolAddress((void**)&pA, g_A);
    cudaGetSymbolAddress((void**)&pB, g_B);

    const int LH[3]   = { 100, 50, 25 };
    const int LW[3]   = { 128, 64, 32 };
    const int LOFF[3] = { 0, 12800, 16000 };
    const long LAYER_W = 256L * 256 * 9;   // per-layer tower conv weight size

    for (int l = 0; l < 3; ++l) {
        const int H = LH[l], W = LW[l], HW = H * W, off = LOFF[l];
        const int tx = (W + TWC - 1) / TWC;
        const int ty = (H + TH - 1) / TH;
        dim3 gT(tx, ty, 8 * 4);   // tower convs: 4 oc tiles of 64
        dim3 gH(tx, ty, 8);       // heads: single oc tile
        const unsigned applyBlocks = (unsigned)((8L * 256 * HW / 4 + 255) / 256);

        // ---- classification tower ----
        conv3x3_k<8, 0><<<gT, 256>>>(feat[l], cls_conv_w, nullptr, cls_conv_b, nullptr,
                                     pA, 256, 256, H, W, 4, 0);
        gn_stats_k<<<128, 256>>>(pA, HW);
        gn_apply_k<<<applyBlocks, 256>>>(pA, cls_gn_g, cls_gn_b, pB, HW);
        conv3x3_k<8, 0><<<gT, 256>>>(pB, cls_conv_w + LAYER_W, nullptr, cls_conv_b + 256, nullptr,
                                     pA, 256, 256, H, W, 4, 0);
        gn_stats_k<<<128, 256>>>(pA, HW);
        gn_apply_k<<<applyBlocks, 256>>>(pA, cls_gn_g + 256, cls_gn_b + 256, pB, HW);
        // cls logits head (OC=20, tile 24)
        conv3x3_k<3, 1><<<gH, 256>>>(pB, cls_out_w, nullptr, cls_out_b, nullptr,
                                     out, 256, 20, H, W, 1, off);

        // ---- regression tower ----
        conv3x3_k<8, 0><<<gT, 256>>>(feat[l], reg_conv_w, nullptr, reg_conv_b, nullptr,
                                     pA, 256, 256, H, W, 4, 0);
        gn_stats_k<<<128, 256>>>(pA, HW);
        gn_apply_k<<<applyBlocks, 256>>>(pA, reg_gn_g, reg_gn_b, pB, HW);
        conv3x3_k<8, 0><<<gT, 256>>>(pB, reg_conv_w + LAYER_W, nullptr, reg_conv_b + 256, nullptr,
                                     pA, 256, 256, H, W, 4, 0);
        gn_stats_k<<<128, 256>>>(pA, HW);
        gn_apply_k<<<applyBlocks, 256>>>(pA, reg_gn_g + 256, reg_gn_b + 256, pB, HW);
        // bbox(4ch, ReLU) + centerness(1ch) head (OC=5, tile 8)
        conv3x3_k<1, 2><<<gH, 256>>>(pB, reg_out_w, ctr_w, reg_out_b, ctr_b,
                                     out, 256, 5, H, W, 1, off);
    }
}

// round 2
// speedup vs baseline: 1.6057x; 1.6057x over previous
#include <cuda_runtime.h>

// ---------------------------------------------------------------------------
// FCOS head: 3 FPN levels, N=8, C=256, GN(16 groups), towers + small heads.
// Round 1: correctness + solid fp32 CUDA-core implicit-GEMM conv.
// ---------------------------------------------------------------------------

#define ICB 8      // input channels per smem chunk
#define TH  8      // tile rows
#define TWC 32     // tile cols (all level widths are multiples of 32)

#define NPIX 16800                 // pixels per batch across all levels
#define REG_BASE 2688000L          // 8*16800*20
#define CTR_BASE 3225600L          // REG_BASE + 8*67200

// Scratch (static device memory: allowed; no cudaMalloc anywhere)
__device__ float g_A[26214400];    // 8*256*100*128
__device__ float g_B[26214400];
__device__ float g_mean[128];      // 8 batches * 16 groups
__device__ float g_rstd[128];

// ---------------------------------------------------------------------------
// conv3x3, stride 1, pad 1. Tile: OCT=8*OCR output channels x (8x32) pixels.
// 256 threads: oc_t = tid&7 (8 oc lanes), px_t = tid>>3 (32 px lanes, 8 px each).
// Per-thread oc are strided (oc_t + 8*i) so weight smem reads are conflict-free.
// MODE 0: plain NCHW store to scratch (tower convs)
// MODE 1: cls head -> out[( n*16800 + off + y*W + x )*20 + oc]
// MODE 2: reg(4ch,ReLU) + ctr(1ch) head -> reg/ctr regions of out
// ---------------------------------------------------------------------------
template<int OCR, int MODE>
__global__ __launch_bounds__(256, 2)
void conv3x3_k(const float* __restrict__ in, const float* __restrict__ w,
               const float* __restrict__ w2,
               const float* __restrict__ bias, const float* __restrict__ bias2,
               float* __restrict__ out,
               int C, int OC, int H, int W, int oc_tiles, int lvlOff)
{
    constexpr int OCT = 8 * OCR;
    __shared__ float sIn[ICB][TH + 2][TWC + 2];
    __shared__ float sW[ICB * 9][OCT];

    const int tid  = threadIdx.x;
    const int oc_t = tid & 7;
    const int px_t = tid >> 3;
    const int r    = px_t >> 2;          // row within tile (0..7)
    const int c0   = (px_t & 3) * 8;     // col group start (0,8,16,24)

    const int n  = blockIdx.z / oc_tiles;
    const int ot = blockIdx.z % oc_tiles;
    const int y0 = blockIdx.y * TH;
    const int x0 = blockIdx.x * TWC;
    const int ocBase = ot * OCT;

    float acc[OCR][8];
#pragma unroll
    for (int i = 0; i < OCR; ++i)
#pragma unroll
        for (int j = 0; j < 8; ++j) acc[i][j] = 0.f;

    const float* __restrict__ inN = in + (long)n * C * H * W;

    for (int ic0 = 0; ic0 < C; ic0 += ICB) {
        __syncthreads();
        // ---- stage input halo tile: ICB x (TH+2) x (TWC+2) ----
        for (int idx = tid; idx < ICB * (TH + 2) * (TWC + 2); idx += 256) {
            int ic  = idx / ((TH + 2) * (TWC + 2));
            int rem = idx % ((TH + 2) * (TWC + 2));
            int ly = rem / (TWC + 2);
            int lx = rem % (TWC + 2);
            int gy = y0 + ly - 1;
            int gx = x0 + lx - 1;
            float v = 0.f;
            if (gy >= 0 && gy < H && gx >= 0 && gx < W)
                v = inN[(long)(ic0 + ic) * H * W + (long)gy * W + gx];
            sIn[ic][ly][lx] = v;
        }
        // ---- stage weights: [ic*9+k][oc_local] ----
        for (int idx = tid; idx < ICB * 9 * OCT; idx += 256) {
            int oc  = idx / (ICB * 9);
            int rem = idx % (ICB * 9);        // ic*9 + k, contiguous in global
            int ocg = ocBase + oc;
            float v = 0.f;
            if (MODE == 2) {
                if (ocg < 4)       v = w [(long)ocg * C * 9 + ic0 * 9 + rem];
                else if (ocg == 4) v = w2[(long)ic0 * 9 + rem];
            } else {
                if (ocg < OC)      v = w [(long)ocg * C * 9 + ic0 * 9 + rem];
            }
            sW[rem][oc] = v;
        }
        __syncthreads();

#pragma unroll 1
        for (int ic = 0; ic < ICB; ++ic) {
#pragma unroll
            for (int ky = 0; ky < 3; ++ky)
#pragma unroll
            for (int kx = 0; kx < 3; ++kx) {
                float a[8];
#pragma unroll
                for (int j = 0; j < 8; ++j) a[j] = sIn[ic][r + ky][c0 + kx + j];
#pragma unroll
                for (int i = 0; i < OCR; ++i) {
                    float wv = sW[ic * 9 + ky * 3 + kx][oc_t + 8 * i];
#pragma unroll
                    for (int j = 0; j < 8; ++j)
                        acc[i][j] = fmaf(wv, a[j], acc[i][j]);
                }
            }
        }
    }

    const int y = y0 + r;
    if (y >= H) return;   // x always in-bounds: W is a multiple of 32

#pragma unroll
    for (int i = 0; i < OCR; ++i) {
        const int ocl = oc_t + 8 * i;
        const int oc  = ocBase + ocl;
        if (MODE == 0) {
            if (oc < OC) {
                float bv = bias[oc];
                float* op = out + ((long)(n * OC + oc) * H + y) * W + x0 + c0;
#pragma unroll
                for (int j = 0; j < 8; ++j) op[j] = acc[i][j] + bv;
            }
        } else if (MODE == 1) {
            if (oc < OC) {
                float bv = bias[oc];
                long pbase = ((long)n * NPIX + lvlOff + (long)y * W + x0 + c0) * 20 + oc;
#pragma unroll
                for (int j = 0; j < 8; ++j) out[pbase + (long)j * 20] = acc[i][j] + bv;
            }
        } else {  // MODE 2
            if (oc < 4) {
                float bv = bias[oc];
                long pbase = REG_BASE + (long)n * 67200
                           + ((long)(lvlOff + y * W + x0 + c0)) * 4 + oc;
#pragma unroll
                for (int j = 0; j < 8; ++j)
                    out[pbase + (long)j * 4] = fmaxf(acc[i][j] + bv, 0.f);
            } else if (oc == 4) {
                float bv = bias2[0];
                long pbase = CTR_BASE + (long)n * NPIX + lvlOff + (long)y * W + x0 + c0;
#pragma unroll
                for (int j = 0; j < 8; ++j) out[pbase + j] = acc[i][j] + bv;
            }
        }
    }
}

// ---------------------------------------------------------------------------
// GroupNorm stats: one block per (n, group). Channels of a group are
// contiguous in NCHW, so each block reduces a contiguous 16*HW span.
// Deterministic (no atomics).
// ---------------------------------------------------------------------------
__global__ void gn_stats_k(const float* __restrict__ x, int HW)
{
    const int n = blockIdx.x >> 4;
    const int g = blockIdx.x & 15;
    const float4* p = (const float4*)(x + ((long)n * 256 + (long)g * 16) * HW);
    const int total4 = (16 * HW) >> 2;

    float s = 0.f, s2 = 0.f;
    for (int i = threadIdx.x; i < total4; i += blockDim.x) {
        float4 v = p[i];
        s  += v.x + v.y + v.z + v.w;
        s2 += v.x * v.x + v.y * v.y + v.z * v.z + v.w * v.w;
    }
    __shared__ float rs[8], rs2[8];
#pragma unroll
    for (int o = 16; o; o >>= 1) {
        s  += __shfl_xor_sync(~0u, s, o);
        s2 += __shfl_xor_sync(~0u, s2, o);
    }
    const int wid = threadIdx.x >> 5, lid = threadIdx.x & 31;
    if (lid == 0) { rs[wid] = s; rs2[wid] = s2; }
    __syncthreads();
    if (wid == 0) {
        s  = (lid < 8) ? rs[lid]  : 0.f;
        s2 = (lid < 8) ? rs2[lid] : 0.f;
#pragma unroll
        for (int o = 4; o; o >>= 1) {
            s  += __shfl_xor_sync(~0u, s, o);
            s2 += __shfl_xor_sync(~0u, s2, o);
        }
        if (lid == 0) {
            float inv = 1.f / (float)(16 * HW);
            float m = s * inv;
            float var = s2 * inv - m * m;
            g_mean[blockIdx.x] = m;
            g_rstd[blockIdx.x] = rsqrtf(var + 1e-5f);
        }
    }
}

// GN apply + ReLU, float4 vectorized (HW is a multiple of 4)
__global__ void gn_apply_k(const float* __restrict__ x,
                           const float* __restrict__ gamma,
                           const float* __restrict__ beta,
                           float* __restrict__ y, int HW)
{
    long idx = (long)blockIdx.x * blockDim.x + threadIdx.x;   // float4 units
    long total4 = (long)8 * 256 * HW / 4;
    if (idx >= total4) return;
    long nc = (idx * 4) / HW;
    int n = (int)(nc >> 8), c = (int)(nc & 255);
    int sg = (n << 4) + (c >> 4);
    float m  = g_mean[sg];
    float rsd = g_rstd[sg];
    float sc = rsd * gamma[c];
    float sh = beta[c] - m * sc;
    float4 v = ((const float4*)x)[idx];
    v.x = fmaxf(v.x * sc + sh, 0.f);
    v.y = fmaxf(v.y * sc + sh, 0.f);
    v.z = fmaxf(v.z * sc + sh, 0.f);
    v.w = fmaxf(v.w * sc + sh, 0.f);
    ((float4*)y)[idx] = v;
}

// ---------------------------------------------------------------------------
extern "C" void kernel_launch(void* const* d_in, const int* in_sizes, int n_in,
                              void* d_out, int out_size)
{
    (void)in_sizes; (void)n_in; (void)out_size;
    const float* feat[3]     = { (const float*)d_in[0], (const float*)d_in[1], (const float*)d_in[2] };
    const float* cls_conv_w  = (const float*)d_in[3];
    const float* cls_conv_b  = (const float*)d_in[4];
    const float* cls_gn_g    = (const float*)d_in[5];
    const float* cls_gn_b    = (const float*)d_in[6];
    const float* cls_out_w   = (const float*)d_in[7];
    const float* cls_out_b   = (const float*)d_in[8];
    const float* reg_conv_w  = (const float*)d_in[9];
    const float* reg_conv_b  = (const float*)d_in[10];
    const float* reg_gn_g    = (const float*)d_in[11];
    const float* reg_gn_b    = (const float*)d_in[12];
    const float* reg_out_w   = (const float*)d_in[13];
    const float* reg_out_b   = (const float*)d_in[14];
    const float* ctr_w       = (const float*)d_in[15];
    const float* ctr_b       = (const float*)d_in[16];
    float* out = (float*)d_out;

    float *pA = nullptr, *pB = nullptr;
    cudaGetSymbolAddress((void**)&pA, g_A);
    cudaGetSymbolAddress((void**)&pB, g_B);

    const int LH[3]   = { 100, 50, 25 };
    const int LW[3]   = { 128, 64, 32 };
    const int LOFF[3] = { 0, 12800, 16000 };
    const long LAYER_W = 256L * 256 * 9;   // per-layer tower conv weight size

    for (int l = 0; l < 3; ++l) {
        const int H = LH[l], W = LW[l], HW = H * W, off = LOFF[l];
        const int tx = (W + TWC - 1) / TWC;
        const int ty = (H + TH - 1) / TH;
        dim3 gT(tx, ty, 8 * 4);   // tower convs: 4 oc tiles of 64
        dim3 gH(tx, ty, 8);       // heads: single oc tile
        const unsigned applyBlocks = (unsigned)((8L * 256 * HW / 4 + 255) / 256);

        // ---- classification tower ----
        conv3x3_k<8, 0><<<gT, 256>>>(feat[l], cls_conv_w, nullptr, cls_conv_b, nullptr,
                                     pA, 256, 256, H, W, 4, 0);
        gn_stats_k<<<128, 256>>>(pA, HW);
        gn_apply_k<<<applyBlocks, 256>>>(pA, cls_gn_g, cls_gn_b, pB, HW);
        conv3x3_k<8, 0><<<gT, 256>>>(pB, cls_conv_w + LAYER_W, nullptr, cls_conv_b + 256, nullptr,
                                     pA, 256, 256, H, W, 4, 0);
        gn_stats_k<<<128, 256>>>(pA, HW);
        gn_apply_k<<<applyBlocks, 256>>>(pA, cls_gn_g + 256, cls_gn_b + 256, pB, HW);
        // cls logits head (OC=20, tile 24)
        conv3x3_k<3, 1><<<gH, 256>>>(pB, cls_out_w, nullptr, cls_out_b, nullptr,
                                     out, 256, 20, H, W, 1, off);

        // ---- regression tower ----
        conv3x3_k<8, 0><<<gT, 256>>>(feat[l], reg_conv_w, nullptr, reg_conv_b, nullptr,
                                     pA, 256, 256, H, W, 4, 0);
        gn_stats_k<<<128, 256>>>(pA, HW);
        gn_apply_k<<<applyBlocks, 256>>>(pA, reg_gn_g, reg_gn_b, pB, HW);
        conv3x3_k<8, 0><<<gT, 256>>>(pB, reg_conv_w + LAYER_W, nullptr, reg_conv_b + 256, nullptr,
                                     pA, 256, 256, H, W, 4, 0);
        gn_stats_k<<<128, 256>>>(pA, HW);
        gn_apply_k<<<applyBlocks, 256>>>(pA, reg_gn_g + 256, reg_gn_b + 256, pB, HW);
        // bbox(4ch, ReLU) + centerness(1ch) head (OC=5, tile 8)
        conv3x3_k<1, 2><<<gH, 256>>>(pB, reg_out_w, ctr_w, reg_out_b, ctr_b,
                                     out, 256, 5, H, W, 1, off);
    }
}

// round 4
// speedup vs baseline: 6.0518x; 3.7689x over previous
#include <cuda_runtime.h>
#include <stdint.h>

#define NPIX 16800
#define REG_BASE 2688000L
#define CTR_BASE 3225600L

// static device scratch (no cudaMalloc anywhere)
__device__ float g_A[26214400];   // NCHW scratch ping
__device__ float g_B[26214400];   // NCHW scratch pong
__device__ float g_W[2949120];    // fragment-ordered tf32 weights
__device__ float g_mean[128];
__device__ float g_rstd[128];

__device__ __forceinline__ float rna_tf32(float f) {
    uint32_t u;
    asm("cvt.rna.tf32.f32 %0, %1;" : "=r"(u) : "f"(f));
    return __uint_as_float(u);
}

__device__ __forceinline__ void mma8(float* c, const uint32_t* a, uint32_t b0, uint32_t b1) {
    asm volatile(
        "mma.sync.aligned.m16n8k8.row.col.f32.tf32.tf32.f32 "
        "{%0,%1,%2,%3}, {%4,%5,%6,%7}, {%8,%9}, {%0,%1,%2,%3};"
        : "+f"(c[0]), "+f"(c[1]), "+f"(c[2]), "+f"(c[3])
        : "r"(a[0]), "r"(a[1]), "r"(a[2]), "r"(a[3]), "r"(b0), "r"(b1));
}

// ---------------------------------------------------------------------------
// tf32 mma.sync conv3x3 s1p1 over NCHW.
// CTA: 128 oc x (4 rows x 32 cols) px. 8 warps, warp = 32 oc x 64 px.
// K = 8 ic-chunks(32) x 9 taps x 4 k-steps(8).
// Halo smem: 32 ic x 6 x 34, plane stride 232 words (== 8 mod 32: B LDS
// banks = 8t + g, conflict-free). A smem: fragment-linear 4096 floats/tap.
// MODE 0: NCHW scratch + bias; 1: cls head (20ch); 2: reg(4ch,ReLU)+ctr(1ch).
// ---------------------------------------------------------------------------
template<int MODE>
__global__ __launch_bounds__(256, 2)
void conv_mma(const float* __restrict__ in, const float* __restrict__ wA,
              const float* __restrict__ bias, const float* __restrict__ bias2,
              float* __restrict__ out, int H, int W, int lvlOff, int OCv)
{
    __shared__ float halo[7424];   // 32 * 232
    __shared__ float sA[4096];

    const int HW  = H * W;
    const int tid = threadIdx.x, wid = tid >> 5, lane = tid & 31;
    const int g = lane >> 2, t = lane & 3;
    const int wm = wid & 3, wn = wid >> 2;
    const int n = blockIdx.z;
    const int ocBase = blockIdx.y * 128;
    const int wtiles = W >> 5;
    const int x0 = (blockIdx.x % wtiles) << 5;
    const int y0 = (blockIdx.x / wtiles) << 2;
    const bool active = (ocBase + wm * 32) < OCv;

    int rcv[8];
#pragma unroll
    for (int nb = 0; nb < 8; ++nb) {
        int px = wn * 64 + nb * 8 + g;
        rcv[nb] = (px >> 5) * 34 + (px & 31);
    }

    float acc[2][8][4];
#pragma unroll
    for (int i = 0; i < 2; ++i)
#pragma unroll
        for (int j = 0; j < 8; ++j)
#pragma unroll
            for (int q = 0; q < 4; ++q) acc[i][j][q] = 0.f;

    const float* __restrict__ inN = in + (long)n * 256 * HW;
    const float* __restrict__ wBase = wA + (long)blockIdx.y * 294912;

    for (int chunk = 0; chunk < 8; ++chunk) {
        __syncthreads();            // prior chunk's B reads done
        // ---- stage halo: 32 ic x 6 x 34, zero-padded border, tf32-rounded ----
        const float* __restrict__ inC = inN + (long)chunk * 32 * HW;
        for (int i = tid; i < 6528; i += 256) {
            int ic = i / 204; int rem = i - ic * 204;
            int ri = rem / 34; int ci = rem - ri * 34;
            int ygl = y0 + ri - 1, xgl = x0 + ci - 1;
            float v = 0.f;
            if ((unsigned)ygl < (unsigned)H && (unsigned)xgl < (unsigned)W)
                v = inC[(long)ic * HW + ygl * W + xgl];
            halo[ic * 232 + ri * 34 + ci] = rna_tf32(v);
        }
        // ---- prefetch A tap 0 ----
        float4 pre[4];
        {
            const float4* gw = (const float4*)(wBase + (long)chunk * 9 * 4096);
#pragma unroll
            for (int j = 0; j < 4; ++j) pre[j] = gw[tid + j * 256];
        }
        for (int tap = 0; tap < 9; ++tap) {
            __syncthreads();        // sA free (and halo ready at tap 0)
#pragma unroll
            for (int j = 0; j < 4; ++j) ((float4*)sA)[tid + j * 256] = pre[j];
            if (tap < 8) {
                const float4* gw = (const float4*)(wBase + ((long)chunk * 9 + tap + 1) * 4096);
#pragma unroll
                for (int j = 0; j < 4; ++j) pre[j] = gw[tid + j * 256];
            }
            __syncthreads();        // sA ready
            if (active) {
                const int tapoff = (tap / 3) * 34 + (tap % 3);
#pragma unroll
                for (int ks = 0; ks < 4; ++ks) {
                    uint4 a0 = *(const uint4*)(sA + ((ks * 8 + wm * 2    ) * 32 + lane) * 4);
                    uint4 a1 = *(const uint4*)(sA + ((ks * 8 + wm * 2 + 1) * 32 + lane) * 4);
                    const float* hb = halo + (ks * 8 + t) * 232 + tapoff;
#pragma unroll
                    for (int nb = 0; nb < 8; ++nb) {
                        uint32_t b0 = __float_as_uint(hb[rcv[nb]]);
                        uint32_t b1 = __float_as_uint(hb[rcv[nb] + 928]);
                        mma8(acc[0][nb], (const uint32_t*)&a0, b0, b1);
                        mma8(acc[1][nb], (const uint32_t*)&a1, b0, b1);
                    }
                }
            }
        }
    }

    if (!active) return;

    // ---- epilogue ----
#pragma unroll
    for (int mbi = 0; mbi < 2; ++mbi) {
        const int ocl = (wm * 2 + mbi) * 16 + g;
        const int oc = ocBase + ocl;
        if (MODE == 0) {
            const float bv0 = bias[oc], bv1 = bias[oc + 8];
            float* o0 = out + (long)(n * 256 + oc) * HW;
#pragma unroll
            for (int nb = 0; nb < 8; ++nb) {
                int pxl = wn * 64 + nb * 8 + 2 * t;
                int ygl = y0 + (pxl >> 5);
                if (ygl >= H) continue;
                long idx = (long)ygl * W + x0 + (pxl & 31);
                *(float2*)(o0 + idx) =
                    make_float2(acc[mbi][nb][0] + bv0, acc[mbi][nb][1] + bv0);
                *(float2*)(o0 + 8L * HW + idx) =
                    make_float2(acc[mbi][nb][2] + bv1, acc[mbi][nb][3] + bv1);
            }
        } else if (MODE == 1) {
#pragma unroll
            for (int nb = 0; nb < 8; ++nb) {
                int pxl = wn * 64 + nb * 8 + 2 * t;
                int ygl = y0 + (pxl >> 5);
                if (ygl >= H) continue;
                int pxg = ygl * W + x0 + (pxl & 31);
                long b = ((long)n * NPIX + lvlOff + pxg) * 20;
                if (oc < 20) {
                    float bv = bias[oc];
                    out[b + oc]      = acc[mbi][nb][0] + bv;
                    out[b + 20 + oc] = acc[mbi][nb][1] + bv;
                }
                if (oc + 8 < 20) {
                    float bv = bias[oc + 8];
                    out[b + oc + 8]      = acc[mbi][nb][2] + bv;
                    out[b + 20 + oc + 8] = acc[mbi][nb][3] + bv;
                }
            }
        } else {
#pragma unroll
            for (int nb = 0; nb < 8; ++nb) {
                int pxl = wn * 64 + nb * 8 + 2 * t;
                int ygl = y0 + (pxl >> 5);
                if (ygl >= H) continue;
                int pxg = ygl * W + x0 + (pxl & 31);
#pragma unroll
                for (int rr = 0; rr < 2; ++rr) {
                    int ocr = oc + rr * 8;
                    float v0 = acc[mbi][nb][rr * 2 + 0];
                    float v1 = acc[mbi][nb][rr * 2 + 1];
                    if (ocr < 4) {
                        float bv = bias[ocr];
                        long rb = REG_BASE + (long)n * 67200 + (long)(lvlOff + pxg) * 4 + ocr;
                        out[rb]     = fmaxf(v0 + bv, 0.f);
                        out[rb + 4] = fmaxf(v1 + bv, 0.f);
                    } else if (ocr == 4) {
                        float bv = bias2[0];
                        long cb = CTR_BASE + (long)n * NPIX + lvlOff + pxg;
                        out[cb]     = v0 + bv;
                        out[cb + 1] = v1 + bv;
                    }
                }
            }
        }
    }
}

// ---------------------------------------------------------------------------
// Weight reorder into fragment-linear order, tf32-rounded.
// dst linear: [ocT][chunk(8)][tap(9)][ks(4)][mb(8)][lane(32)][j(4)]
// oc = ocT*128 + mb*16 + g + (j&1)*8 ;  ic = chunk*32 + ks*8 + t + ((j>>1)&1)*4
// ---------------------------------------------------------------------------
__global__ void reorder_frag(const float* __restrict__ w, const float* __restrict__ wctr,
                             float* __restrict__ dst, int OC, int total)
{
    int d = blockIdx.x * 256 + threadIdx.x;
    if (d >= total) return;
    int j = d & 3; int r = d >> 2;
    int lane = r & 31; r >>= 5;
    int mb = r & 7;  r >>= 3;
    int ks = r & 3;  r >>= 2;
    int tap = r % 9; r /= 9;
    int chunk = r & 7; r >>= 3;
    int ocT = r;
    int g = lane >> 2, t = lane & 3;
    int oc = ocT * 128 + mb * 16 + g + (j & 1) * 8;
    int ic = chunk * 32 + ks * 8 + t + ((j >> 1) & 1) * 4;
    float v = 0.f;
    if (oc < OC) v = w[((long)oc * 256 + ic) * 9 + tap];
    else if (wctr != nullptr && oc == OC) v = wctr[(long)ic * 9 + tap];
    dst[d] = rna_tf32(v);
}

// ---------------------------------------------------------------------------
// GroupNorm (NCHW) — stats then apply+ReLU (verified in R1)
// ---------------------------------------------------------------------------
__global__ void gn_stats_k(const float* __restrict__ x, int HW)
{
    const int n = blockIdx.x >> 4;
    const int g = blockIdx.x & 15;
    const float4* p = (const float4*)(x + ((long)n * 256 + (long)g * 16) * HW);
    const int total4 = (16 * HW) >> 2;
    float s = 0.f, s2 = 0.f;
    for (int i = threadIdx.x; i < total4; i += blockDim.x) {
        float4 v = p[i];
        s  += v.x + v.y + v.z + v.w;
        s2 += v.x * v.x + v.y * v.y + v.z * v.z + v.w * v.w;
    }
    __shared__ float rs[8], rs2[8];
#pragma unroll
    for (int o = 16; o; o >>= 1) {
        s  += __shfl_xor_sync(~0u, s, o);
        s2 += __shfl_xor_sync(~0u, s2, o);
    }
    const int w = threadIdx.x >> 5, l = threadIdx.x & 31;
    if (l == 0) { rs[w] = s; rs2[w] = s2; }
    __syncthreads();
    if (w == 0) {
        s  = (l < 8) ? rs[l]  : 0.f;
        s2 = (l < 8) ? rs2[l] : 0.f;
#pragma unroll
        for (int o = 4; o; o >>= 1) {
            s  += __shfl_xor_sync(~0u, s, o);
            s2 += __shfl_xor_sync(~0u, s2, o);
        }
        if (l == 0) {
            float inv = 1.f / (float)(16 * HW);
            float m = s * inv;
            g_mean[blockIdx.x] = m;
            g_rstd[blockIdx.x] = rsqrtf(s2 * inv - m * m + 1e-5f);
        }
    }
}

__global__ void gn_apply_k(const float* __restrict__ x, const float* __restrict__ gamma,
                           const float* __restrict__ beta, float* __restrict__ y, int HW)
{
    long idx = (long)blockIdx.x * blockDim.x + threadIdx.x;
    long total4 = (long)8 * 256 * HW / 4;
    if (idx >= total4) return;
    long nc = (idx * 4) / HW;
    int n = (int)(nc >> 8), c = (int)(nc & 255);
    int sg = (n << 4) + (c >> 4);
    float m = g_mean[sg], rsd = g_rstd[sg];
    float sc = rsd * gamma[c];
    float sh = beta[c] - m * sc;
    float4 v = ((const float4*)x)[idx];
    v.x = fmaxf(v.x * sc + sh, 0.f);
    v.y = fmaxf(v.y * sc + sh, 0.f);
    v.z = fmaxf(v.z * sc + sh, 0.f);
    v.w = fmaxf(v.w * sc + sh, 0.f);
    ((float4*)y)[idx] = v;
}

// ---------------------------------------------------------------------------
extern "C" void kernel_launch(void* const* d_in, const int* in_sizes, int n_in,
                              void* d_out, int out_size)
{
    (void)in_sizes; (void)n_in; (void)out_size;
    const float* feat[3] = { (const float*)d_in[0], (const float*)d_in[1], (const float*)d_in[2] };
    const float* cls_conv_w = (const float*)d_in[3];
    const float* cls_conv_b = (const float*)d_in[4];
    const float* cls_gn_g = (const float*)d_in[5];
    const float* cls_gn_b = (const float*)d_in[6];
    const float* cls_out_w = (const float*)d_in[7];
    const float* cls_out_b = (const float*)d_in[8];
    const float* reg_conv_w = (const float*)d_in[9];
    const float* reg_conv_b = (const float*)d_in[10];
    const float* reg_gn_g = (const float*)d_in[11];
    const float* reg_gn_b = (const float*)d_in[12];
    const float* reg_out_w = (const float*)d_in[13];
    const float* reg_out_b = (const float*)d_in[14];
    const float* ctr_w = (const float*)d_in[15];
    const float* ctr_b = (const float*)d_in[16];
    float* out = (float*)d_out;

    float *pA, *pB, *pW;
    cudaGetSymbolAddress((void**)&pA, g_A);
    cudaGetSymbolAddress((void**)&pB, g_B);
    cudaGetSymbolAddress((void**)&pW, g_W);

    // ---- weight reorders (fragment-linear, tf32) ----
    reorder_frag<<<2304, 256>>>(cls_conv_w,          nullptr, pW,           256, 589824);
    reorder_frag<<<2304, 256>>>(cls_conv_w + 589824, nullptr, pW + 589824,  256, 589824);
    reorder_frag<<<2304, 256>>>(reg_conv_w,          nullptr, pW + 1179648, 256, 589824);
    reorder_frag<<<2304, 256>>>(reg_conv_w + 589824, nullptr, pW + 1769472, 256, 589824);
    reorder_frag<<<1152, 256>>>(cls_out_w,           nullptr, pW + 2359296,  20, 294912);
    reorder_frag<<<1152, 256>>>(reg_out_w,           ctr_w,   pW + 2654208,   4, 294912);

    const int LH[3] = { 100, 50, 25 };
    const int LW[3] = { 128, 64, 32 };
    const int LOFF[3] = { 0, 12800, 16000 };

    for (int l = 0; l < 3; ++l) {
        const int H = LH[l], W = LW[l], HW = H * W, off = LOFF[l];
        const int wt = W >> 5, ht = (H + 3) >> 2;
        dim3 gT(wt * ht, 2, 8), gH(wt * ht, 1, 8);
        const unsigned ab = (unsigned)((8L * 256 * HW / 4 + 255) / 256);

        // ---- classification tower ----
        conv_mma<0><<<gT, 256>>>(feat[l], pW, cls_conv_b, nullptr, pA, H, W, 0, 256);
        gn_stats_k<<<128, 256>>>(pA, HW);
        gn_apply_k<<<ab, 256>>>(pA, cls_gn_g, cls_gn_b, pB, HW);
        conv_mma<0><<<gT, 256>>>(pB, pW + 589824, cls_conv_b + 256, nullptr, pA, H, W, 0, 256);
        gn_stats_k<<<128, 256>>>(pA, HW);
        gn_apply_k<<<ab, 256>>>(pA, cls_gn_g + 256, cls_gn_b + 256, pB, HW);
        conv_mma<1><<<gH, 256>>>(pB, pW + 2359296, cls_out_b, nullptr, out, H, W, off, 20);

        // ---- regression tower ----
        conv_mma<0><<<gT, 256>>>(feat[l], pW + 1179648, reg_conv_b, nullptr, pA, H, W, 0, 256);
        gn_stats_k<<<128, 256>>>(pA, HW);
        gn_apply_k<<<ab, 256>>>(pA, reg_gn_g, reg_gn_b, pB, HW);
        conv_mma<0><<<gT, 256>>>(pB, pW + 1769472, reg_conv_b + 256, nullptr, pA, H, W, 0, 256);
        gn_stats_k<<<128, 256>>>(pA, HW);
        gn_apply_k<<<ab, 256>>>(pA, reg_gn_g + 256, reg_gn_b + 256, pB, HW);
        conv_mma<2><<<gH, 256>>>(pB, pW + 2654208, reg_out_b, ctr_b, out, H, W, off, 5);
    }
}

// round 5
// speedup vs baseline: 6.1726x; 1.0200x over previous
#include <cuda_runtime.h>
#include <cuda_fp16.h>
#include <stdint.h>

#define NPIX 16800
#define REG_BASE 2688000L
#define CTR_BASE 3225600L

// static device scratch (no cudaMalloc anywhere)
__device__ float    g_A[26214400];     // NCHW conv-output ping
__device__ float    g_B[26214400];     // NCHW conv-output pong
__device__ uint32_t g_W[1474560];      // fragment-ordered half2 weights
__device__ float    g_mean[128];
__device__ float    g_rstd[128];

__device__ __forceinline__ void mma16(float* c, const uint32_t* a, uint32_t b0, uint32_t b1) {
    asm volatile(
        "mma.sync.aligned.m16n8k16.row.col.f32.f16.f16.f32 "
        "{%0,%1,%2,%3}, {%4,%5,%6,%7}, {%8,%9}, {%0,%1,%2,%3};"
        : "+f"(c[0]), "+f"(c[1]), "+f"(c[2]), "+f"(c[3])
        : "r"(a[0]), "r"(a[1]), "r"(a[2]), "r"(a[3]), "r"(b0), "r"(b1));
}

// ---------------------------------------------------------------------------
// fp16 mma.sync conv3x3 s1p1 over NCHW, optional fused GN+ReLU on the input.
// CTA: 128 oc x (4 rows x 32 cols) px. 8 warps, warp = 32 oc x 64 px.
// K = 8 ic-chunks(32) x 9 taps x 2 k16-steps.
// Halo: 16 half2-planes (ic pairs) x 6 x 34, plane stride 232 words
//   (== 8 mod 32 -> B LDS banks = 8t+g conflict-free; +4 planes == 0 mod 32).
// A smem: fragment-linear 2048 uint32 per tap, prefetched one tap ahead.
// MODE 0: NCHW scratch + bias; 1: cls head (20ch); 2: reg(4,ReLU)+ctr(1).
// GN 1: staging applies (x-m)*rstd*gamma+beta then ReLU (zero-pad AFTER GN).
// ---------------------------------------------------------------------------
template<int MODE, int GN>
__global__ __launch_bounds__(256, 2)
void conv_mma(const float* __restrict__ in, const uint32_t* __restrict__ wA,
              const float* __restrict__ bias, const float* __restrict__ bias2,
              const float* __restrict__ gamma, const float* __restrict__ beta,
              float* __restrict__ out, int H, int W, int lvlOff, int OCv)
{
    __shared__ uint32_t halo[3712];   // 16 * 232 (half2 each)
    __shared__ uint32_t sA[2048];     // one tap of A fragments

    const int HW  = H * W;
    const int tid = threadIdx.x, wid = tid >> 5, lane = tid & 31;
    const int g = lane >> 2, t = lane & 3;
    const int wm = wid & 3, wn = wid >> 2;
    const int n = blockIdx.z;
    const int ocBase = blockIdx.y * 128;
    const int wtiles = W >> 5;
    const int x0 = (blockIdx.x % wtiles) << 5;
    const int y0 = (blockIdx.x / wtiles) << 2;
    const bool active = (ocBase + wm * 32) < OCv;

    int rcv[8];
#pragma unroll
    for (int nb = 0; nb < 8; ++nb) {
        int px = wn * 64 + nb * 8 + g;
        rcv[nb] = (px >> 5) * 34 + (px & 31);
    }

    float acc[2][8][4];
#pragma unroll
    for (int i = 0; i < 2; ++i)
#pragma unroll
        for (int j = 0; j < 8; ++j)
#pragma unroll
            for (int q = 0; q < 4; ++q) acc[i][j][q] = 0.f;

    const float* __restrict__ inN = in + (long)n * 256 * HW;
    const uint32_t* __restrict__ wBase = wA + (long)blockIdx.y * 147456;

    for (int chunk = 0; chunk < 8; ++chunk) {
        __syncthreads();            // prior chunk's halo reads done
        // ---- stage halo: 16 half2-planes x 6 x 34, GN fused, zero border ----
        const float* __restrict__ inC = inN + (long)chunk * 32 * HW;
        for (int i = tid; i < 3264; i += 256) {
            int p = i / 204; int rem = i - p * 204;
            int ri = rem / 34; int ci = rem - ri * 34;
            int ygl = y0 + ri - 1, xgl = x0 + ci - 1;
            float v0 = 0.f, v1 = 0.f;
            if ((unsigned)ygl < (unsigned)H && (unsigned)xgl < (unsigned)W) {
                long bidx = (long)(2 * p) * HW + (long)ygl * W + xgl;
                v0 = inC[bidx];
                v1 = inC[bidx + HW];
                if (GN) {
                    int c = chunk * 32 + 2 * p;
                    int sg = n * 16 + (c >> 4);
                    float m = g_mean[sg], rs = g_rstd[sg];
                    v0 = fmaxf((v0 - m) * rs * gamma[c]     + beta[c],     0.f);
                    v1 = fmaxf((v1 - m) * rs * gamma[c + 1] + beta[c + 1], 0.f);
                }
            }
            __half2 h = __floats2half2_rn(v0, v1);
            halo[p * 232 + ri * 34 + ci] = *(uint32_t*)&h;
        }
        // ---- prefetch A tap 0 ----
        uint4 pre[2];
        {
            const uint4* gw = (const uint4*)(wBase + (long)chunk * 9 * 2048);
#pragma unroll
            for (int j = 0; j < 2; ++j) pre[j] = gw[tid + j * 256];
        }
        for (int tap = 0; tap < 9; ++tap) {
            __syncthreads();        // sA free (and halo ready at tap 0)
#pragma unroll
            for (int j = 0; j < 2; ++j) ((uint4*)sA)[tid + j * 256] = pre[j];
            if (tap < 8) {
                const uint4* gw = (const uint4*)(wBase + ((long)chunk * 9 + tap + 1) * 2048);
#pragma unroll
                for (int j = 0; j < 2; ++j) pre[j] = gw[tid + j * 256];
            }
            __syncthreads();        // sA ready
            if (active) {
                const int tapoff = (tap / 3) * 34 + (tap % 3);
#pragma unroll
                for (int ks = 0; ks < 2; ++ks) {
                    uint4 a0 = *(const uint4*)(sA + ((ks * 8 + wm * 2    ) * 32 + lane) * 4);
                    uint4 a1 = *(const uint4*)(sA + ((ks * 8 + wm * 2 + 1) * 32 + lane) * 4);
                    const uint32_t* hb = halo + (ks * 8 + t) * 232 + tapoff;
#pragma unroll
                    for (int nb = 0; nb < 8; ++nb) {
                        uint32_t b0 = hb[rcv[nb]];
                        uint32_t b1 = hb[rcv[nb] + 928];   // +4 planes
                        mma16(acc[0][nb], (const uint32_t*)&a0, b0, b1);
                        mma16(acc[1][nb], (const uint32_t*)&a1, b0, b1);
                    }
                }
            }
        }
    }

    if (!active) return;

    // ---- epilogue (C layout identical to m16n8k8) ----
#pragma unroll
    for (int mbi = 0; mbi < 2; ++mbi) {
        const int ocl = (wm * 2 + mbi) * 16 + g;
        const int oc = ocBase + ocl;
        if (MODE == 0) {
            const float bv0 = bias[oc], bv1 = bias[oc + 8];
            float* o0 = out + (long)(n * 256 + oc) * HW;
#pragma unroll
            for (int nb = 0; nb < 8; ++nb) {
                int pxl = wn * 64 + nb * 8 + 2 * t;
                int ygl = y0 + (pxl >> 5);
                if (ygl >= H) continue;
                long idx = (long)ygl * W + x0 + (pxl & 31);
                *(float2*)(o0 + idx) =
                    make_float2(acc[mbi][nb][0] + bv0, acc[mbi][nb][1] + bv0);
                *(float2*)(o0 + 8L * HW + idx) =
                    make_float2(acc[mbi][nb][2] + bv1, acc[mbi][nb][3] + bv1);
            }
        } else if (MODE == 1) {
#pragma unroll
            for (int nb = 0; nb < 8; ++nb) {
                int pxl = wn * 64 + nb * 8 + 2 * t;
                int ygl = y0 + (pxl >> 5);
                if (ygl >= H) continue;
                int pxg = ygl * W + x0 + (pxl & 31);
                long b = ((long)n * NPIX + lvlOff + pxg) * 20;
                if (oc < 20) {
                    float bv = bias[oc];
                    out[b + oc]      = acc[mbi][nb][0] + bv;
                    out[b + 20 + oc] = acc[mbi][nb][1] + bv;
                }
                if (oc + 8 < 20) {
                    float bv = bias[oc + 8];
                    out[b + oc + 8]      = acc[mbi][nb][2] + bv;
                    out[b + 20 + oc + 8] = acc[mbi][nb][3] + bv;
                }
            }
        } else {
#pragma unroll
            for (int nb = 0; nb < 8; ++nb) {
                int pxl = wn * 64 + nb * 8 + 2 * t;
                int ygl = y0 + (pxl >> 5);
                if (ygl >= H) continue;
                int pxg = ygl * W + x0 + (pxl & 31);
#pragma unroll
                for (int rr = 0; rr < 2; ++rr) {
                    int ocr = oc + rr * 8;
                    float v0 = acc[mbi][nb][rr * 2 + 0];
                    float v1 = acc[mbi][nb][rr * 2 + 1];
                    if (ocr < 4) {
                        float bv = bias[ocr];
                        long rb = REG_BASE + (long)n * 67200 + (long)(lvlOff + pxg) * 4 + ocr;
                        out[rb]     = fmaxf(v0 + bv, 0.f);
                        out[rb + 4] = fmaxf(v1 + bv, 0.f);
                    } else if (ocr == 4) {
                        float bv = bias2[0];
                        long cb = CTR_BASE + (long)n * NPIX + lvlOff + pxg;
                        out[cb]     = v0 + bv;
                        out[cb + 1] = v1 + bv;
                    }
                }
            }
        }
    }
}

// ---------------------------------------------------------------------------
// Weight reorder -> fragment-linear half2.
// d: [ocT][chunk(8)][tap(9)][ks(2)][mb(8)][lane(32)][reg(4)] (uint32 each)
// oc = ocT*128 + mb*16 + lane/4 + (reg&1)*8
// icp = chunk*32 + ks*16 + (lane&3)*2 + ((reg>>1)&1)*8 ; half2 = (icp, icp+1)
// ---------------------------------------------------------------------------
__global__ void reorder_frag(const float* __restrict__ w, const float* __restrict__ wctr,
                             uint32_t* __restrict__ dst, int OC, int total)
{
    int d = blockIdx.x * 256 + threadIdx.x;
    if (d >= total) return;
    int j = d & 3; int r = d >> 2;
    int lane = r & 31; r >>= 5;
    int mb = r & 7;  r >>= 3;
    int ks = r & 1;  r >>= 1;
    int tap = r % 9; r /= 9;
    int chunk = r & 7; r >>= 3;
    int ocT = r;
    int oc  = ocT * 128 + mb * 16 + (lane >> 2) + (j & 1) * 8;
    int icp = chunk * 32 + ks * 16 + (lane & 3) * 2 + ((j >> 1) & 1) * 8;
    float v0 = 0.f, v1 = 0.f;
    if (oc < OC) {
        v0 = w[((long)oc * 256 + icp) * 9 + tap];
        v1 = w[((long)oc * 256 + icp + 1) * 9 + tap];
    } else if (wctr != nullptr && oc == OC) {
        v0 = wctr[(long)icp * 9 + tap];
        v1 = wctr[(long)(icp + 1) * 9 + tap];
    }
    __half2 h = __floats2half2_rn(v0, v1);
    dst[d] = *(uint32_t*)&h;
}

// ---------------------------------------------------------------------------
// GroupNorm stats over NCHW (deterministic, block per (n,group))
// ---------------------------------------------------------------------------
__global__ void gn_stats_k(const float* __restrict__ x, int HW)
{
    const int n = blockIdx.x >> 4;
    const int g = blockIdx.x & 15;
    const float4* p = (const float4*)(x + ((long)n * 256 + (long)g * 16) * HW);
    const int total4 = (16 * HW) >> 2;
    float s = 0.f, s2 = 0.f;
    for (int i = threadIdx.x; i < total4; i += blockDim.x) {
        float4 v = p[i];
        s  += v.x + v.y + v.z + v.w;
        s2 += v.x * v.x + v.y * v.y + v.z * v.z + v.w * v.w;
    }
    __shared__ float rs[8], rs2[8];
#pragma unroll
    for (int o = 16; o; o >>= 1) {
        s  += __shfl_xor_sync(~0u, s, o);
        s2 += __shfl_xor_sync(~0u, s2, o);
    }
    const int w = threadIdx.x >> 5, l = threadIdx.x & 31;
    if (l == 0) { rs[w] = s; rs2[w] = s2; }
    __syncthreads();
    if (w == 0) {
        s  = (l < 8) ? rs[l]  : 0.f;
        s2 = (l < 8) ? rs2[l] : 0.f;
#pragma unroll
        for (int o = 4; o; o >>= 1) {
            s  += __shfl_xor_sync(~0u, s, o);
            s2 += __shfl_xor_sync(~0u, s2, o);
        }
        if (l == 0) {
            float inv = 1.f / (float)(16 * HW);
            float m = s * inv;
            g_mean[blockIdx.x] = m;
            g_rstd[blockIdx.x] = rsqrtf(s2 * inv - m * m + 1e-5f);
        }
    }
}

// ---------------------------------------------------------------------------
extern "C" void kernel_launch(void* const* d_in, const int* in_sizes, int n_in,
                              void* d_out, int out_size)
{
    (void)in_sizes; (void)n_in; (void)out_size;
    const float* feat[3] = { (const float*)d_in[0], (const float*)d_in[1], (const float*)d_in[2] };
    const float* cls_conv_w = (const float*)d_in[3];
    const float* cls_conv_b = (const float*)d_in[4];
    const float* cls_gn_g = (const float*)d_in[5];
    const float* cls_gn_b = (const float*)d_in[6];
    const float* cls_out_w = (const float*)d_in[7];
    const float* cls_out_b = (const float*)d_in[8];
    const float* reg_conv_w = (const float*)d_in[9];
    const float* reg_conv_b = (const float*)d_in[10];
    const float* reg_gn_g = (const float*)d_in[11];
    const float* reg_gn_b = (const float*)d_in[12];
    const float* reg_out_w = (const float*)d_in[13];
    const float* reg_out_b = (const float*)d_in[14];
    const float* ctr_w = (const float*)d_in[15];
    const float* ctr_b = (const float*)d_in[16];
    float* out = (float*)d_out;

    float *pA, *pB;
    uint32_t* pW;
    cudaGetSymbolAddress((void**)&pA, g_A);
    cudaGetSymbolAddress((void**)&pB, g_B);
    cudaGetSymbolAddress((void**)&pW, g_W);

    // ---- weight reorders (fragment-linear half2) ----
    reorder_frag<<<1152, 256>>>(cls_conv_w,          nullptr, pW,           256, 294912);
    reorder_frag<<<1152, 256>>>(cls_conv_w + 589824, nullptr, pW + 294912,  256, 294912);
    reorder_frag<<<1152, 256>>>(reg_conv_w,          nullptr, pW + 589824,  256, 294912);
    reorder_frag<<<1152, 256>>>(reg_conv_w + 589824, nullptr, pW + 884736,  256, 294912);
    reorder_frag<<< 576, 256>>>(cls_out_w,           nullptr, pW + 1179648,  20, 147456);
    reorder_frag<<< 576, 256>>>(reg_out_w,           ctr_w,   pW + 1327104,   4, 147456);

    const int LH[3] = { 100, 50, 25 };
    const int LW[3] = { 128, 64, 32 };
    const int LOFF[3] = { 0, 12800, 16000 };

    for (int l = 0; l < 3; ++l) {
        const int H = LH[l], W = LW[l], HW = H * W, off = LOFF[l];
        const int wt = W >> 5, ht = (H + 3) >> 2;
        dim3 gT(wt * ht, 2, 8), gH(wt * ht, 1, 8);

        // ---- classification tower (GN fused into conv staging) ----
        conv_mma<0, 0><<<gT, 256>>>(feat[l], pW, cls_conv_b, nullptr,
                                    nullptr, nullptr, pA, H, W, 0, 256);
        gn_stats_k<<<128, 256>>>(pA, HW);
        conv_mma<0, 1><<<gT, 256>>>(pA, pW + 294912, cls_conv_b + 256, nullptr,
                                    cls_gn_g, cls_gn_b, pB, H, W, 0, 256);
        gn_stats_k<<<128, 256>>>(pB, HW);
        conv_mma<1, 1><<<gH, 256>>>(pB, pW + 1179648, cls_out_b, nullptr,
                                    cls_gn_g + 256, cls_gn_b + 256, out, H, W, off, 20);

        // ---- regression tower ----
        conv_mma<0, 0><<<gT, 256>>>(feat[l], pW + 589824, reg_conv_b, nullptr,
                                    nullptr, nullptr, pA, H, W, 0, 256);
        gn_stats_k<<<128, 256>>>(pA, HW);
        conv_mma<0, 1><<<gT, 256>>>(pA, pW + 884736, reg_conv_b + 256, nullptr,
                                    reg_gn_g, reg_gn_b, pB, H, W, 0, 256);
        gn_stats_k<<<128, 256>>>(pB, HW);
        conv_mma<2, 1><<<gH, 256>>>(pB, pW + 1327104, reg_out_b, ctr_b,
                                    reg_gn_g + 256, reg_gn_b + 256, out, H, W, off, 5);
    }
}

// round 6
// speedup vs baseline: 6.9806x; 1.1309x over previous
#include <cuda_runtime.h>
#include <cuda_fp16.h>
#include <stdint.h>

#define NPIX 16800
#define REG_BASE 2688000L
#define CTR_BASE 3225600L

// static device scratch (no cudaMalloc anywhere)
__device__ float    g_A[26214400];     // NCHW conv-output ping
__device__ float    g_B[26214400];     // NCHW conv-output pong
__device__ uint32_t g_W[1474560];      // fragment-ordered half2 weights
__device__ float    g_mean[128];
__device__ float    g_rstd[128];

__device__ __forceinline__ void mma16(float* c, const uint32_t* a, uint32_t b0, uint32_t b1) {
    asm volatile(
        "mma.sync.aligned.m16n8k16.row.col.f32.f16.f16.f32 "
        "{%0,%1,%2,%3}, {%4,%5,%6,%7}, {%8,%9}, {%0,%1,%2,%3};"
        : "+f"(c[0]), "+f"(c[1]), "+f"(c[2]), "+f"(c[3])
        : "r"(a[0]), "r"(a[1]), "r"(a[2]), "r"(a[3]), "r"(b0), "r"(b1));
}

// ---------------------------------------------------------------------------
// fp16 mma.sync conv3x3 s1p1 over NCHW, fused GN+ReLU on input, fully
// software-pipelined:
//   - A tap tiles double-buffered in smem -> ONE __syncthreads per tap
//   - halo double-buffered; next chunk's halo staged in 9 slices spread
//     across the current chunk's taps (global latency hidden behind MMA)
//   - next tap's A global loads issued before the MMA block
// CTA: 128 oc x (4 rows x 32 cols). 8 warps = 32 oc x 64 px each.
// Halo plane stride 232 words (==8 mod 32 -> B LDS conflict-free).
// MODE 0: NCHW scratch + bias; 1: cls head(20ch); 2: reg(4,ReLU)+ctr(1).
// ---------------------------------------------------------------------------
template<int MODE, int GN>
__global__ __launch_bounds__(256, 2)
void conv_mma(const float* __restrict__ in, const uint32_t* __restrict__ wA,
              const float* __restrict__ bias, const float* __restrict__ bias2,
              const float* __restrict__ gamma, const float* __restrict__ beta,
              float* __restrict__ out, int H, int W, int lvlOff, int OCv)
{
    __shared__ uint32_t halo[2][3712];   // 16 half2-planes x 232, x2 buffers
    __shared__ uint32_t sA[2][2048];     // A tap fragments, double-buffered

    const int HW  = H * W;
    const int tid = threadIdx.x, wid = tid >> 5, lane = tid & 31;
    const int g = lane >> 2, t = lane & 3;
    const int wm = wid & 3, wn = wid >> 2;
    const int n = blockIdx.z;
    const int ocBase = blockIdx.y * 128;
    const int wtiles = W >> 5;
    const int x0 = (blockIdx.x % wtiles) << 5;
    const int y0 = (blockIdx.x / wtiles) << 2;
    const bool active = (ocBase + wm * 32) < OCv;

    int rcv[8];
#pragma unroll
    for (int nb = 0; nb < 8; ++nb) {
        int px = wn * 64 + nb * 8 + g;
        rcv[nb] = (px >> 5) * 34 + (px & 31);
    }

    float acc[2][8][4];
#pragma unroll
    for (int i = 0; i < 2; ++i)
#pragma unroll
        for (int j = 0; j < 8; ++j)
#pragma unroll
            for (int q = 0; q < 4; ++q) acc[i][j][q] = 0.f;

    const float* __restrict__ inN = in + (long)n * 256 * HW;
    const uint32_t* __restrict__ wBase = wA + (long)blockIdx.y * 147456;

    // halo slice staging (GN fused, zero-pad after GN)
    auto stage = [&](int chunk, int hb, int lo, int hi) {
        const float* __restrict__ inC = inN + (long)chunk * 32 * HW;
        for (int i = lo + tid; i < hi; i += 256) {
            int p = i / 204; int rem = i - p * 204;
            int ri = rem / 34; int ci = rem - ri * 34;
            int ygl = y0 + ri - 1, xgl = x0 + ci - 1;
            float v0 = 0.f, v1 = 0.f;
            if ((unsigned)ygl < (unsigned)H && (unsigned)xgl < (unsigned)W) {
                long bidx = (long)(2 * p) * HW + (long)ygl * W + xgl;
                v0 = inC[bidx];
                v1 = inC[bidx + HW];
                if (GN) {
                    int c = chunk * 32 + 2 * p;
                    int sg = n * 16 + (c >> 4);
                    float m = g_mean[sg], rs = g_rstd[sg];
                    v0 = fmaxf((v0 - m) * rs * gamma[c]     + beta[c],     0.f);
                    v1 = fmaxf((v1 - m) * rs * gamma[c + 1] + beta[c + 1], 0.f);
                }
            }
            __half2 h = __floats2half2_rn(v0, v1);
            halo[hb][p * 232 + ri * 34 + ci] = *(uint32_t*)&h;
        }
    };

    // ---- prologue: chunk-0 halo into buf0, tap-0 A into sA[0] ----
    stage(0, 0, 0, 3264);
    {
        const uint4* gw = (const uint4*)wBase;
        ((uint4*)sA[0])[tid]       = gw[tid];
        ((uint4*)sA[0])[tid + 256] = gw[tid + 256];
    }
    __syncthreads();

    // ---- main loop: one barrier per tap ----
    for (int cid = 0; cid < 72; ++cid) {
        const int chunk = cid / 9, tap = cid - chunk * 9;
        const int buf = cid & 1, hbuf = chunk & 1;

        // issue next-tap A global loads early (L2 latency overlaps MMA)
        uint4 pre0, pre1;
        if (cid < 71) {
            const uint4* gw = (const uint4*)(wBase + (long)(cid + 1) * 2048);
            pre0 = gw[tid];
            pre1 = gw[tid + 256];
        }

        if (active) {
            const int tapoff = (tap / 3) * 34 + (tap % 3);
            const uint32_t* hB = halo[hbuf];
#pragma unroll
            for (int ks = 0; ks < 2; ++ks) {
                uint4 a0 = *(const uint4*)(sA[buf] + ((ks * 8 + wm * 2    ) * 32 + lane) * 4);
                uint4 a1 = *(const uint4*)(sA[buf] + ((ks * 8 + wm * 2 + 1) * 32 + lane) * 4);
                const uint32_t* hb = hB + (ks * 8 + t) * 232 + tapoff;
#pragma unroll
                for (int nb = 0; nb < 8; ++nb) {
                    uint32_t b0 = hb[rcv[nb]];
                    uint32_t b1 = hb[rcv[nb] + 928];   // +4 planes
                    mma16(acc[0][nb], (const uint32_t*)&a0, b0, b1);
                    mma16(acc[1][nb], (const uint32_t*)&a1, b0, b1);
                }
            }
        }

        // store next-tap A into the other buffer
        if (cid < 71) {
            ((uint4*)sA[buf ^ 1])[tid]       = pre0;
            ((uint4*)sA[buf ^ 1])[tid + 256] = pre1;
        }
        // stage 1/9 slice of next chunk's halo into the other halo buffer
        if (chunk < 7) {
            int lo = tap * 368;
            int hi = lo + 368; if (hi > 3264) hi = 3264;
            stage(chunk + 1, hbuf ^ 1, lo, hi);
        }
        __syncthreads();
    }

    if (!active) return;

    // ---- epilogue ----
#pragma unroll
    for (int mbi = 0; mbi < 2; ++mbi) {
        const int ocl = (wm * 2 + mbi) * 16 + g;
        const int oc = ocBase + ocl;
        if (MODE == 0) {
            const float bv0 = bias[oc], bv1 = bias[oc + 8];
            float* o0 = out + (long)(n * 256 + oc) * HW;
#pragma unroll
            for (int nb = 0; nb < 8; ++nb) {
                int pxl = wn * 64 + nb * 8 + 2 * t;
                int ygl = y0 + (pxl >> 5);
                if (ygl >= H) continue;
                long idx = (long)ygl * W + x0 + (pxl & 31);
                *(float2*)(o0 + idx) =
                    make_float2(acc[mbi][nb][0] + bv0, acc[mbi][nb][1] + bv0);
                *(float2*)(o0 + 8L * HW + idx) =
                    make_float2(acc[mbi][nb][2] + bv1, acc[mbi][nb][3] + bv1);
            }
        } else if (MODE == 1) {
#pragma unroll
            for (int nb = 0; nb < 8; ++nb) {
                int pxl = wn * 64 + nb * 8 + 2 * t;
                int ygl = y0 + (pxl >> 5);
                if (ygl >= H) continue;
                int pxg = ygl * W + x0 + (pxl & 31);
                long b = ((long)n * NPIX + lvlOff + pxg) * 20;
                if (oc < 20) {
                    float bv = bias[oc];
                    out[b + oc]      = acc[mbi][nb][0] + bv;
                    out[b + 20 + oc] = acc[mbi][nb][1] + bv;
                }
                if (oc + 8 < 20) {
                    float bv = bias[oc + 8];
                    out[b + oc + 8]      = acc[mbi][nb][2] + bv;
                    out[b + 20 + oc + 8] = acc[mbi][nb][3] + bv;
                }
            }
        } else {
#pragma unroll
            for (int nb = 0; nb < 8; ++nb) {
                int pxl = wn * 64 + nb * 8 + 2 * t;
                int ygl = y0 + (pxl >> 5);
                if (ygl >= H) continue;
                int pxg = ygl * W + x0 + (pxl & 31);
#pragma unroll
                for (int rr = 0; rr < 2; ++rr) {
                    int ocr = oc + rr * 8;
                    float v0 = acc[mbi][nb][rr * 2 + 0];
                    float v1 = acc[mbi][nb][rr * 2 + 1];
                    if (ocr < 4) {
                        float bv = bias[ocr];
                        long rb = REG_BASE + (long)n * 67200 + (long)(lvlOff + pxg) * 4 + ocr;
                        out[rb]     = fmaxf(v0 + bv, 0.f);
                        out[rb + 4] = fmaxf(v1 + bv, 0.f);
                    } else if (ocr == 4) {
                        float bv = bias2[0];
                        long cb = CTR_BASE + (long)n * NPIX + lvlOff + pxg;
                        out[cb]     = v0 + bv;
                        out[cb + 1] = v1 + bv;
                    }
                }
            }
        }
    }
}

// ---------------------------------------------------------------------------
// Weight reorders -> fragment-linear half2 (3 launches total so ncu lands
// on a conv). Fragment decode:
// d: [r][chunk(8)][tap(9)][ks(2)][mb(8)][lane(32)][reg(4)] (uint32 each)
// oc = (r&1)*128 + mb*16 + lane/4 + (reg&1)*8
// icp = chunk*32 + ks*16 + (lane&3)*2 + ((reg>>1)&1)*8 ; half2=(icp,icp+1)
// ---------------------------------------------------------------------------
__device__ __forceinline__ void frag_decode(int d, int& r, int& chunk, int& tap,
                                            int& oc128, int& icp)
{
    int j = d & 3; int q = d >> 2;
    int lane = q & 31; q >>= 5;
    int mb = q & 7;  q >>= 3;
    int ks = q & 1;  q >>= 1;
    tap = q % 9; q /= 9;
    chunk = q & 7; q >>= 3;
    r = q;
    oc128 = mb * 16 + (lane >> 2) + (j & 1) * 8;
    icp   = chunk * 32 + ks * 16 + (lane & 3) * 2 + ((j >> 1) & 1) * 8;
}

// two tower layers of one head (w = [2][256][256][3][3])
__global__ void reorder_tower(const float* __restrict__ w, uint32_t* __restrict__ dst)
{
    int d = blockIdx.x * 256 + threadIdx.x;
    if (d >= 589824) return;
    int r, chunk, tap, oc128, icp;
    frag_decode(d, r, chunk, tap, oc128, icp);
    int layer = r >> 1;
    int oc = (r & 1) * 128 + oc128;
    const float* src = w + (long)layer * 589824;
    float v0 = src[((long)oc * 256 + icp) * 9 + tap];
    float v1 = src[((long)oc * 256 + icp + 1) * 9 + tap];
    __half2 h = __floats2half2_rn(v0, v1);
    dst[d] = *(uint32_t*)&h;
}

// both head convs: r=0 -> cls_out (OC=20), r=1 -> reg_out(4)+ctr(1)
__global__ void reorder_heads(const float* __restrict__ wcls, const float* __restrict__ wreg,
                              const float* __restrict__ wctr, uint32_t* __restrict__ dst)
{
    int d = blockIdx.x * 256 + threadIdx.x;
    if (d >= 294912) return;
    int r, chunk, tap, oc128, icp;
    frag_decode(d, r, chunk, tap, oc128, icp);
    int oc = oc128;
    float v0 = 0.f, v1 = 0.f;
    if (r == 0) {
        if (oc < 20) {
            v0 = wcls[((long)oc * 256 + icp) * 9 + tap];
            v1 = wcls[((long)oc * 256 + icp + 1) * 9 + tap];
        }
    } else {
        if (oc < 4) {
            v0 = wreg[((long)oc * 256 + icp) * 9 + tap];
            v1 = wreg[((long)oc * 256 + icp + 1) * 9 + tap];
        } else if (oc == 4) {
            v0 = wctr[(long)icp * 9 + tap];
            v1 = wctr[(long)(icp + 1) * 9 + tap];
        }
    }
    __half2 h = __floats2half2_rn(v0, v1);
    dst[d] = *(uint32_t*)&h;
}

// ---------------------------------------------------------------------------
// GroupNorm stats over NCHW (deterministic, block per (n,group))
// ---------------------------------------------------------------------------
__global__ void gn_stats_k(const float* __restrict__ x, int HW)
{
    const int n = blockIdx.x >> 4;
    const int g = blockIdx.x & 15;
    const float4* p = (const float4*)(x + ((long)n * 256 + (long)g * 16) * HW);
    const int total4 = (16 * HW) >> 2;
    float s = 0.f, s2 = 0.f;
    for (int i = threadIdx.x; i < total4; i += blockDim.x) {
        float4 v = p[i];
        s  += v.x + v.y + v.z + v.w;
        s2 += v.x * v.x + v.y * v.y + v.z * v.z + v.w * v.w;
    }
    __shared__ float rs[8], rs2[8];
#pragma unroll
    for (int o = 16; o; o >>= 1) {
        s  += __shfl_xor_sync(~0u, s, o);
        s2 += __shfl_xor_sync(~0u, s2, o);
    }
    const int w = threadIdx.x >> 5, l = threadIdx.x & 31;
    if (l == 0) { rs[w] = s; rs2[w] = s2; }
    __syncthreads();
    if (w == 0) {
        s  = (l < 8) ? rs[l]  : 0.f;
        s2 = (l < 8) ? rs2[l] : 0.f;
#pragma unroll
        for (int o = 4; o; o >>= 1) {
            s  += __shfl_xor_sync(~0u, s, o);
            s2 += __shfl_xor_sync(~0u, s2, o);
        }
        if (l == 0) {
            float inv = 1.f / (float)(16 * HW);
            float m = s * inv;
            g_mean[blockIdx.x] = m;
            g_rstd[blockIdx.x] = rsqrtf(s2 * inv - m * m + 1e-5f);
        }
    }
}

// ---------------------------------------------------------------------------
extern "C" void kernel_launch(void* const* d_in, const int* in_sizes, int n_in,
                              void* d_out, int out_size)
{
    (void)in_sizes; (void)n_in; (void)out_size;
    const float* feat[3] = { (const float*)d_in[0], (const float*)d_in[1], (const float*)d_in[2] };
    const float* cls_conv_w = (const float*)d_in[3];
    const float* cls_conv_b = (const float*)d_in[4];
    const float* cls_gn_g = (const float*)d_in[5];
    const float* cls_gn_b = (const float*)d_in[6];
    const float* cls_out_w = (const float*)d_in[7];
    const float* cls_out_b = (const float*)d_in[8];
    const float* reg_conv_w = (const float*)d_in[9];
    const float* reg_conv_b = (const float*)d_in[10];
    const float* reg_gn_g = (const float*)d_in[11];
    const float* reg_gn_b = (const float*)d_in[12];
    const float* reg_out_w = (const float*)d_in[13];
    const float* reg_out_b = (const float*)d_in[14];
    const float* ctr_w = (const float*)d_in[15];
    const float* ctr_b = (const float*)d_in[16];
    float* out = (float*)d_out;

    float *pA, *pB;
    uint32_t* pW;
    cudaGetSymbolAddress((void**)&pA, g_A);
    cudaGetSymbolAddress((void**)&pB, g_B);
    cudaGetSymbolAddress((void**)&pW, g_W);

    // ---- 3 reorder launches (ncu -s 5 then lands on launch #6: a GN-fused
    //      level-0 tower conv) ----
    reorder_tower<<<2304, 256>>>(cls_conv_w, pW);
    reorder_tower<<<2304, 256>>>(reg_conv_w, pW + 589824);
    reorder_heads<<<1152, 256>>>(cls_out_w, reg_out_w, ctr_w, pW + 1179648);

    const int LH[3] = { 100, 50, 25 };
    const int LW[3] = { 128, 64, 32 };
    const int LOFF[3] = { 0, 12800, 16000 };

    for (int l = 0; l < 3; ++l) {
        const int H = LH[l], W = LW[l], HW = H * W, off = LOFF[l];
        const int wt = W >> 5, ht = (H + 3) >> 2;
        dim3 gT(wt * ht, 2, 8), gH(wt * ht, 1, 8);

        // ---- classification tower (GN fused into conv staging) ----
        conv_mma<0, 0><<<gT, 256>>>(feat[l], pW, cls_conv_b, nullptr,
                                    nullptr, nullptr, pA, H, W, 0, 256);
        gn_stats_k<<<128, 256>>>(pA, HW);
        conv_mma<0, 1><<<gT, 256>>>(pA, pW + 294912, cls_conv_b + 256, nullptr,
                                    cls_gn_g, cls_gn_b, pB, H, W, 0, 256);
        gn_stats_k<<<128, 256>>>(pB, HW);
        conv_mma<1, 1><<<gH, 256>>>(pB, pW + 1179648, cls_out_b, nullptr,
                                    cls_gn_g + 256, cls_gn_b + 256, out, H, W, off, 20);

        // ---- regression tower ----
        conv_mma<0, 0><<<gT, 256>>>(feat[l], pW + 589824, reg_conv_b, nullptr,
                                    nullptr, nullptr, pA, H, W, 0, 256);
        gn_stats_k<<<128, 256>>>(pA, HW);
        conv_mma<0, 1><<<gT, 256>>>(pA, pW + 884736, reg_conv_b + 256, nullptr,
                                    reg_gn_g, reg_gn_b, pB, H, W, 0, 256);
        gn_stats_k<<<128, 256>>>(pB, HW);
        conv_mma<2, 1><<<gH, 256>>>(pB, pW + 1327104, reg_out_b, ctr_b,
                                    reg_gn_g + 256, reg_gn_b + 256, out, H, W, off, 5);
    }
}

// round 7
// speedup vs baseline: 7.8173x; 1.1199x over previous
#include <cuda_runtime.h>
#include <cuda_fp16.h>
#include <stdint.h>

#define NPIX 16800
#define REG_BASE 2688000L
#define CTR_BASE 3225600L

// static device scratch (no cudaMalloc anywhere)
__device__ float    g_A[26214400];     // NCHW conv-output ping
__device__ float    g_B[26214400];     // NCHW conv-output pong
__device__ uint32_t g_W[1474560];      // fragment-ordered half2 weights
__device__ float    g_mean[128];
__device__ float    g_rstd[128];

__device__ __forceinline__ uint32_t smem_u32(const void* p) {
    uint32_t a;
    asm("{ .reg .u64 t; cvta.to.shared.u64 t, %1; cvt.u32.u64 %0, t; }" : "=r"(a) : "l"(p));
    return a;
}
__device__ __forceinline__ void mma16(float* c, const uint32_t* a, uint32_t b0, uint32_t b1) {
    asm volatile(
        "mma.sync.aligned.m16n8k16.row.col.f32.f16.f16.f32 "
        "{%0,%1,%2,%3}, {%4,%5,%6,%7}, {%8,%9}, {%0,%1,%2,%3};"
        : "+f"(c[0]), "+f"(c[1]), "+f"(c[2]), "+f"(c[3])
        : "r"(a[0]), "r"(a[1]), "r"(a[2]), "r"(a[3]), "r"(b0), "r"(b1));
}
__device__ __forceinline__ void ldsm4(uint32_t* r, uint32_t addr) {
    asm volatile("ldmatrix.sync.aligned.m8n8.x4.shared.b16 {%0,%1,%2,%3}, [%4];"
        : "=r"(r[0]), "=r"(r[1]), "=r"(r[2]), "=r"(r[3]) : "r"(addr));
}

// ---------------------------------------------------------------------------
// fp16 mma.sync conv3x3 s1p1 over NCHW, fused GN+ReLU on input.
//  - B operand: pixel-major halo (20 words = 80B per pixel, ldmatrix rows
//    conflict-free: stride 20 mod 32 partitions 32 banks), ldmatrix.x4.
//  - A operand: fragment-linear global, per-thread LDG.128, reg double-buffer
//    (no smem for A at all).
//  - ONE __syncthreads per ic-chunk (8+1 total); halo double-buffered, next
//    chunk staged in 9 slices across the current chunk's taps.
// CTA: 128 oc x (4 rows x 32 cols). Warp = 32 oc x 64 px (wm oc, wn px).
// MODE 0: NCHW scratch + bias; 1: cls head(20ch); 2: reg(4,ReLU)+ctr(1).
// ---------------------------------------------------------------------------
template<int MODE, int GN>
__global__ __launch_bounds__(256, 2)
void conv_mma(const float* __restrict__ in, const uint32_t* __restrict__ wA,
              const float* __restrict__ bias, const float* __restrict__ bias2,
              const float* __restrict__ gamma, const float* __restrict__ beta,
              float* __restrict__ out, int H, int W, int lvlOff, int OCv)
{
    __shared__ uint32_t halo[2][4080];   // 204 px * 20 words, double-buffered

    const int HW  = H * W;
    const int tid = threadIdx.x, wid = tid >> 5, lane = tid & 31;
    const int g = lane >> 2, t = lane & 3;
    const int wm = wid & 3, wn = wid >> 2;
    const int n = blockIdx.z;
    const int ocBase = blockIdx.y * 128;
    const int wtiles = W >> 5;
    const int x0 = (blockIdx.x % wtiles) << 5;
    const int y0 = (blockIdx.x / wtiles) << 2;
    const bool active = (ocBase + wm * 32) < OCv;

    // ldmatrix per-lane base addresses: matrix m=lane>>3 -> (nb = 2p+(m>>1),
    // khalf = m&1); row r = lane&7 -> pixel wn*64 + nb*8 + r.
    const int mm = lane >> 3, rr = lane & 7;
    const uint32_t sbase = smem_u32(halo);
    uint32_t bAddr[4];
#pragma unroll
    for (int p = 0; p < 4; ++p) {
        int pxl = wn * 64 + (2 * p + (mm >> 1)) * 8 + rr;
        bAddr[p] = sbase + (uint32_t)((((pxl >> 5) * 34 + (pxl & 31)) * 20 + (mm & 1) * 4) * 4);
    }

    float acc[2][8][4];
#pragma unroll
    for (int i = 0; i < 2; ++i)
#pragma unroll
        for (int j = 0; j < 8; ++j)
#pragma unroll
            for (int q = 0; q < 4; ++q) acc[i][j][q] = 0.f;

    const float* __restrict__ inN = in + (long)n * 256 * HW;
    const uint4* __restrict__ wf4 = (const uint4*)(wA + (long)blockIdx.y * 147456);

    // halo slice staging: item i -> (word w = i/204, pixel px = i%204);
    // coalesced LDG (consecutive ci), pixel-major STS.
    auto stage = [&](int chunk, int hb, int lo, int hi) {
        const float* __restrict__ inC = inN + (long)chunk * 32 * HW;
        for (int i = lo + tid; i < hi; i += 256) {
            int w = i / 204; int px = i - w * 204;
            int ri = px / 34, ci = px - ri * 34;
            int ygl = y0 + ri - 1, xgl = x0 + ci - 1;
            float v0 = 0.f, v1 = 0.f;
            if ((unsigned)ygl < (unsigned)H && (unsigned)xgl < (unsigned)W) {
                long bidx = (long)(2 * w) * HW + (long)ygl * W + xgl;
                v0 = inC[bidx];
                v1 = inC[bidx + HW];
                if (GN) {
                    int c = chunk * 32 + 2 * w;
                    int sg = n * 16 + (c >> 4);
                    float m = g_mean[sg], rs = g_rstd[sg];
                    v0 = fmaxf((v0 - m) * rs * gamma[c]     + beta[c],     0.f);
                    v1 = fmaxf((v1 - m) * rs * gamma[c + 1] + beta[c + 1], 0.f);
                }
            }
            __half2 h = __floats2half2_rn(v0, v1);
            halo[hb][px * 20 + w] = *(uint32_t*)&h;
        }
    };

    // ---- prologue: chunk-0 halo, tap-0 A fragments ----
    stage(0, 0, 0, 3264);
    uint4 Ac[4];
    if (active) {
#pragma unroll
        for (int q = 0; q < 4; ++q)
            Ac[q] = wf4[(q >> 1) * 256 + (wm * 2 + (q & 1)) * 32 + lane];
    }
    __syncthreads();

    for (int chunk = 0; chunk < 8; ++chunk) {
        const int hb = chunk & 1;
        const uint32_t hoff = (uint32_t)hb * 16320u;
        for (int tap = 0; tap < 9; ++tap) {
            const int cid = chunk * 9 + tap;
            // prefetch next tap's A fragments (regs only, no sync needed)
            uint4 An[4];
            if (active && cid < 71) {
                const uint4* wf = wf4 + (long)(cid + 1) * 512;
#pragma unroll
                for (int q = 0; q < 4; ++q)
                    An[q] = wf[(q >> 1) * 256 + (wm * 2 + (q & 1)) * 32 + lane];
            }
            if (active) {
                const uint32_t toff = hoff + (uint32_t)(((tap / 3) * 34 + (tap % 3)) * 80);
#pragma unroll
                for (int ks = 0; ks < 2; ++ks) {
                    const uint32_t o2 = toff + ks * 32;
#pragma unroll
                    for (int p = 0; p < 4; ++p) {
                        uint32_t b[4];
                        ldsm4(b, bAddr[p] + o2);
                        mma16(acc[0][2 * p],     (const uint32_t*)&Ac[ks * 2],     b[0], b[1]);
                        mma16(acc[1][2 * p],     (const uint32_t*)&Ac[ks * 2 + 1], b[0], b[1]);
                        mma16(acc[0][2 * p + 1], (const uint32_t*)&Ac[ks * 2],     b[2], b[3]);
                        mma16(acc[1][2 * p + 1], (const uint32_t*)&Ac[ks * 2 + 1], b[2], b[3]);
                    }
                }
            }
            // stage a slice of next chunk's halo into the other buffer
            if (chunk < 7) {
                int lo = tap * 368;
                int hi = lo + 368; if (hi > 3264) hi = 3264;
                stage(chunk + 1, hb ^ 1, lo, hi);
            }
            if (active && cid < 71) {
                Ac[0] = An[0]; Ac[1] = An[1]; Ac[2] = An[2]; Ac[3] = An[3];
            }
        }
        __syncthreads();   // halo buffer swap
    }

    if (!active) return;

    // ---- epilogue (C frag: row=oc=g(+8), col=pixel=2t(+1)) ----
#pragma unroll
    for (int mbi = 0; mbi < 2; ++mbi) {
        const int ocl = (wm * 2 + mbi) * 16 + g;
        const int oc = ocBase + ocl;
        if (MODE == 0) {
            const float bv0 = bias[oc], bv1 = bias[oc + 8];
            float* o0 = out + (long)(n * 256 + oc) * HW;
#pragma unroll
            for (int nb = 0; nb < 8; ++nb) {
                int pxl = wn * 64 + nb * 8 + 2 * t;
                int ygl = y0 + (pxl >> 5);
                if (ygl >= H) continue;
                long idx = (long)ygl * W + x0 + (pxl & 31);
                *(float2*)(o0 + idx) =
                    make_float2(acc[mbi][nb][0] + bv0, acc[mbi][nb][1] + bv0);
                *(float2*)(o0 + 8L * HW + idx) =
                    make_float2(acc[mbi][nb][2] + bv1, acc[mbi][nb][3] + bv1);
            }
        } else if (MODE == 1) {
#pragma unroll
            for (int nb = 0; nb < 8; ++nb) {
                int pxl = wn * 64 + nb * 8 + 2 * t;
                int ygl = y0 + (pxl >> 5);
                if (ygl >= H) continue;
                int pxg = ygl * W + x0 + (pxl & 31);
                long b = ((long)n * NPIX + lvlOff + pxg) * 20;
                if (oc < 20) {
                    float bv = bias[oc];
                    out[b + oc]      = acc[mbi][nb][0] + bv;
                    out[b + 20 + oc] = acc[mbi][nb][1] + bv;
                }
                if (oc + 8 < 20) {
                    float bv = bias[oc + 8];
                    out[b + oc + 8]      = acc[mbi][nb][2] + bv;
                    out[b + 20 + oc + 8] = acc[mbi][nb][3] + bv;
                }
            }
        } else {
#pragma unroll
            for (int nb = 0; nb < 8; ++nb) {
                int pxl = wn * 64 + nb * 8 + 2 * t;
                int ygl = y0 + (pxl >> 5);
                if (ygl >= H) continue;
                int pxg = ygl * W + x0 + (pxl & 31);
#pragma unroll
                for (int rrj = 0; rrj < 2; ++rrj) {
                    int ocr = oc + rrj * 8;
                    float v0 = acc[mbi][nb][rrj * 2 + 0];
                    float v1 = acc[mbi][nb][rrj * 2 + 1];
                    if (ocr < 4) {
                        float bv = bias[ocr];
                        long rb = REG_BASE + (long)n * 67200 + (long)(lvlOff + pxg) * 4 + ocr;
                        out[rb]     = fmaxf(v0 + bv, 0.f);
                        out[rb + 4] = fmaxf(v1 + bv, 0.f);
                    } else if (ocr == 4) {
                        float bv = bias2[0];
                        long cb = CTR_BASE + (long)n * NPIX + lvlOff + pxg;
                        out[cb]     = v0 + bv;
                        out[cb + 1] = v1 + bv;
                    }
                }
            }
        }
    }
}

// ---------------------------------------------------------------------------
// Weight reorders -> fragment-linear half2.
// d: [r][chunk(8)][tap(9)][ks(2)][mb(8)][lane(32)][reg(4)] (uint32 each)
// oc = (r&1)*128 + mb*16 + lane/4 + (reg&1)*8
// icp = chunk*32 + ks*16 + (lane&3)*2 + ((reg>>1)&1)*8 ; half2=(icp,icp+1)
// ---------------------------------------------------------------------------
__device__ __forceinline__ void frag_decode(int d, int& r, int& chunk, int& tap,
                                            int& oc128, int& icp)
{
    int j = d & 3; int q = d >> 2;
    int lane = q & 31; q >>= 5;
    int mb = q & 7;  q >>= 3;
    int ks = q & 1;  q >>= 1;
    tap = q % 9; q /= 9;
    chunk = q & 7; q >>= 3;
    r = q;
    oc128 = mb * 16 + (lane >> 2) + (j & 1) * 8;
    icp   = chunk * 32 + ks * 16 + (lane & 3) * 2 + ((j >> 1) & 1) * 8;
}

__global__ void reorder_tower(const float* __restrict__ w, uint32_t* __restrict__ dst)
{
    int d = blockIdx.x * 256 + threadIdx.x;
    if (d >= 589824) return;
    int r, chunk, tap, oc128, icp;
    frag_decode(d, r, chunk, tap, oc128, icp);
    int layer = r >> 1;
    int oc = (r & 1) * 128 + oc128;
    const float* src = w + (long)layer * 589824;
    float v0 = src[((long)oc * 256 + icp) * 9 + tap];
    float v1 = src[((long)oc * 256 + icp + 1) * 9 + tap];
    __half2 h = __floats2half2_rn(v0, v1);
    dst[d] = *(uint32_t*)&h;
}

__global__ void reorder_heads(const float* __restrict__ wcls, const float* __restrict__ wreg,
                              const float* __restrict__ wctr, uint32_t* __restrict__ dst)
{
    int d = blockIdx.x * 256 + threadIdx.x;
    if (d >= 294912) return;
    int r, chunk, tap, oc128, icp;
    frag_decode(d, r, chunk, tap, oc128, icp);
    int oc = oc128;
    float v0 = 0.f, v1 = 0.f;
    if (r == 0) {
        if (oc < 20) {
            v0 = wcls[((long)oc * 256 + icp) * 9 + tap];
            v1 = wcls[((long)oc * 256 + icp + 1) * 9 + tap];
        }
    } else {
        if (oc < 4) {
            v0 = wreg[((long)oc * 256 + icp) * 9 + tap];
            v1 = wreg[((long)oc * 256 + icp + 1) * 9 + tap];
        } else if (oc == 4) {
            v0 = wctr[(long)icp * 9 + tap];
            v1 = wctr[(long)(icp + 1) * 9 + tap];
        }
    }
    __half2 h = __floats2half2_rn(v0, v1);
    dst[d] = *(uint32_t*)&h;
}

// ---------------------------------------------------------------------------
// GroupNorm stats over NCHW (deterministic, block per (n,group))
// ---------------------------------------------------------------------------
__global__ void gn_stats_k(const float* __restrict__ x, int HW)
{
    const int n = blockIdx.x >> 4;
    const int g = blockIdx.x & 15;
    const float4* p = (const float4*)(x + ((long)n * 256 + (long)g * 16) * HW);
    const int total4 = (16 * HW) >> 2;
    float s = 0.f, s2 = 0.f;
    for (int i = threadIdx.x; i < total4; i += blockDim.x) {
        float4 v = p[i];
        s  += v.x + v.y + v.z + v.w;
        s2 += v.x * v.x + v.y * v.y + v.z * v.z + v.w * v.w;
    }
    __shared__ float rs[8], rs2[8];
#pragma unroll
    for (int o = 16; o; o >>= 1) {
        s  += __shfl_xor_sync(~0u, s, o);
        s2 += __shfl_xor_sync(~0u, s2, o);
    }
    const int w = threadIdx.x >> 5, l = threadIdx.x & 31;
    if (l == 0) { rs[w] = s; rs2[w] = s2; }
    __syncthreads();
    if (w == 0) {
        s  = (l < 8) ? rs[l]  : 0.f;
        s2 = (l < 8) ? rs2[l] : 0.f;
#pragma unroll
        for (int o = 4; o; o >>= 1) {
            s  += __shfl_xor_sync(~0u, s, o);
            s2 += __shfl_xor_sync(~0u, s2, o);
        }
        if (l == 0) {
            float inv = 1.f / (float)(16 * HW);
            float m = s * inv;
            g_mean[blockIdx.x] = m;
            g_rstd[blockIdx.x] = rsqrtf(s2 * inv - m * m + 1e-5f);
        }
    }
}

// ---------------------------------------------------------------------------
extern "C" void kernel_launch(void* const* d_in, const int* in_sizes, int n_in,
                              void* d_out, int out_size)
{
    (void)in_sizes; (void)n_in; (void)out_size;
    const float* feat[3] = { (const float*)d_in[0], (const float*)d_in[1], (const float*)d_in[2] };
    const float* cls_conv_w = (const float*)d_in[3];
    const float* cls_conv_b = (const float*)d_in[4];
    const float* cls_gn_g = (const float*)d_in[5];
    const float* cls_gn_b = (const float*)d_in[6];
    const float* cls_out_w = (const float*)d_in[7];
    const float* cls_out_b = (const float*)d_in[8];
    const float* reg_conv_w = (const float*)d_in[9];
    const float* reg_conv_b = (const float*)d_in[10];
    const float* reg_gn_g = (const float*)d_in[11];
    const float* reg_gn_b = (const float*)d_in[12];
    const float* reg_out_w = (const float*)d_in[13];
    const float* reg_out_b = (const float*)d_in[14];
    const float* ctr_w = (const float*)d_in[15];
    const float* ctr_b = (const float*)d_in[16];
    float* out = (float*)d_out;

    float *pA, *pB;
    uint32_t* pW;
    cudaGetSymbolAddress((void**)&pA, g_A);
    cudaGetSymbolAddress((void**)&pB, g_B);
    cudaGetSymbolAddress((void**)&pW, g_W);

    reorder_tower<<<2304, 256>>>(cls_conv_w, pW);
    reorder_tower<<<2304, 256>>>(reg_conv_w, pW + 589824);
    reorder_heads<<<1152, 256>>>(cls_out_w, reg_out_w, ctr_w, pW + 1179648);

    const int LH[3] = { 100, 50, 25 };
    const int LW[3] = { 128, 64, 32 };
    const int LOFF[3] = { 0, 12800, 16000 };

    for (int l = 0; l < 3; ++l) {
        const int H = LH[l], W = LW[l], HW = H * W, off = LOFF[l];
        const int wt = W >> 5, ht = (H + 3) >> 2;
        dim3 gT(wt * ht, 2, 8), gH(wt * ht, 1, 8);

        // ---- classification tower (GN fused into conv staging) ----
        conv_mma<0, 0><<<gT, 256>>>(feat[l], pW, cls_conv_b, nullptr,
                                    nullptr, nullptr, pA, H, W, 0, 256);
        gn_stats_k<<<128, 256>>>(pA, HW);
        conv_mma<0, 1><<<gT, 256>>>(pA, pW + 294912, cls_conv_b + 256, nullptr,
                                    cls_gn_g, cls_gn_b, pB, H, W, 0, 256);
        gn_stats_k<<<128, 256>>>(pB, HW);
        conv_mma<1, 1><<<gH, 256>>>(pB, pW + 1179648, cls_out_b, nullptr,
                                    cls_gn_g + 256, cls_gn_b + 256, out, H, W, off, 20);

        // ---- regression tower ----
        conv_mma<0, 0><<<gT, 256>>>(feat[l], pW + 589824, reg_conv_b, nullptr,
                                    nullptr, nullptr, pA, H, W, 0, 256);
        gn_stats_k<<<128, 256>>>(pA, HW);
        conv_mma<0, 1><<<gT, 256>>>(pA, pW + 884736, reg_conv_b + 256, nullptr,
                                    reg_gn_g, reg_gn_b, pB, H, W, 0, 256);
        gn_stats_k<<<128, 256>>>(pB, HW);
        conv_mma<2, 1><<<gH, 256>>>(pB, pW + 1327104, reg_out_b, ctr_b,
                                    reg_gn_g + 256, reg_gn_b + 256, out, H, W, off, 5);
    }
}

// round 8
// speedup vs baseline: 10.4797x; 1.3406x over previous
#include <cuda_runtime.h>
#include <cuda_fp16.h>
#include <stdint.h>

#define NPIX 16800
#define REG_BASE 2688000L
#define CTR_BASE 3225600L

// static device scratch (no cudaMalloc anywhere). Per-level regions inside
// each buffer: level l at SOFF[l], size 8*256*HW_l floats.
#define BUF_FLOATS 34406400L
__device__ float    g_A[BUF_FLOATS];   // cls conv1 out
__device__ float    g_B[BUF_FLOATS];   // cls conv2 out
__device__ float    g_C[BUF_FLOATS];   // reg conv1 out
__device__ float    g_D[BUF_FLOATS];   // reg conv2 out
__device__ uint32_t g_W[1474560];      // fragment-ordered half2 weights
__device__ float    g_mean[768];       // [tower*3+level][n*16+g]
__device__ float    g_rstd[768];

__device__ __forceinline__ uint32_t smem_u32(const void* p) {
    uint32_t a;
    asm("{ .reg .u64 t; cvta.to.shared.u64 t, %1; cvt.u32.u64 %0, t; }" : "=r"(a) : "l"(p));
    return a;
}
__device__ __forceinline__ void mma16(float* c, const uint32_t* a, uint32_t b0, uint32_t b1) {
    asm volatile(
        "mma.sync.aligned.m16n8k16.row.col.f32.f16.f16.f32 "
        "{%0,%1,%2,%3}, {%4,%5,%6,%7}, {%8,%9}, {%0,%1,%2,%3};"
        : "+f"(c[0]), "+f"(c[1]), "+f"(c[2]), "+f"(c[3])
        : "r"(a[0]), "r"(a[1]), "r"(a[2]), "r"(a[3]), "r"(b0), "r"(b1));
}
__device__ __forceinline__ void ldsm4(uint32_t* r, uint32_t addr) {
    asm volatile("ldmatrix.sync.aligned.m8n8.x4.shared.b16 {%0,%1,%2,%3}, [%4];"
        : "=r"(r[0]), "=r"(r[1]), "=r"(r[2]), "=r"(r[3]) : "r"(addr));
}

// ---------------------------------------------------------------------------
// Merged fp16 mma.sync conv3x3 s1p1 (NCHW), all levels x both towers in one
// launch per stage. Per-CTA decode: blockIdx.x -> (level, pixel tile),
// blockIdx.y -> (tower, oc tile), blockIdx.z -> batch.
//  STAGE 0: conv1 (no GN), feats -> A/C
//  STAGE 1: conv2 (GN layer0 fused), A/C -> B/D
//  STAGE 2: heads (GN layer1 fused), B/D -> final output (cls / reg+ctr)
// Inner loop identical to R7 (ldmatrix B from pixel-major halo, A fragments
// straight from global with register double-buffer, 1 barrier per chunk).
// ---------------------------------------------------------------------------
template<int STAGE>
__global__ __launch_bounds__(256, 2)
void conv_mma(const float* __restrict__ f0, const float* __restrict__ f1,
              const float* __restrict__ f2, const uint32_t* __restrict__ wAll,
              const float* __restrict__ b_cls, const float* __restrict__ b_reg,
              const float* __restrict__ b_ctr,
              const float* __restrict__ g_cls, const float* __restrict__ be_cls,
              const float* __restrict__ g_reg, const float* __restrict__ be_reg,
              float* __restrict__ out_cls, float* __restrict__ out_reg)
{
    // ---- level decode ----
    const int bx = blockIdx.x;
    int l, tile, H, W, wt;
    if (bx < 100)      { l = 0; tile = bx;       H = 100; W = 128; wt = 4; }
    else if (bx < 126) { l = 1; tile = bx - 100; H = 50;  W = 64;  wt = 2; }
    else               { l = 2; tile = bx - 126; H = 25;  W = 32;  wt = 1; }
    const int HW = H * W;
    const long SOFF[3]  = { 0L, 26214400L, 32768000L };
    const int  OOFF[3]  = { 0, 12800, 16000 };

    // ---- tower / oc-tile decode ----
    int tower, ocTile;
    if (STAGE == 2) { tower = blockIdx.y; ocTile = 0; }
    else            { tower = blockIdx.y >> 1; ocTile = blockIdx.y & 1; }
    const int OCv = (STAGE == 2) ? (tower ? 5 : 20) : 256;

    const int tid = threadIdx.x, wid = tid >> 5, lane = tid & 31;
    const int g = lane >> 2, t = lane & 3;
    const int wm = wid & 3, wn = wid >> 2;
    const int n = blockIdx.z;
    const int ocBase = ocTile * 128;
    const int x0 = (tile % wt) << 5;
    const int y0 = (tile / wt) << 2;
    const bool active = (ocBase + wm * 32) < OCv;

    __shared__ uint32_t halo[2][4080];   // 204 px * 20 words, double-buffered

    // ldmatrix per-lane base addresses
    const int mm = lane >> 3, rr = lane & 7;
    const uint32_t sbase = smem_u32(halo);
    uint32_t bAddr[4];
#pragma unroll
    for (int p = 0; p < 4; ++p) {
        int pxl = wn * 64 + (2 * p + (mm >> 1)) * 8 + rr;
        bAddr[p] = sbase + (uint32_t)((((pxl >> 5) * 34 + (pxl & 31)) * 20 + (mm & 1) * 4) * 4);
    }

    float acc[2][8][4];
#pragma unroll
    for (int i = 0; i < 2; ++i)
#pragma unroll
        for (int j = 0; j < 8; ++j)
#pragma unroll
            for (int q = 0; q < 4; ++q) acc[i][j][q] = 0.f;

    // ---- input / weight / GN pointers ----
    const float* inL;
    if (STAGE == 0) inL = ((l == 0) ? f0 : (l == 1) ? f1 : f2) + (long)n * 256 * HW;
    else            inL = (tower ? f1 : f0) + SOFF[l] + (long)n * 256 * HW;
    const uint32_t* wA;
    if (STAGE == 0)      wA = wAll + tower * 589824;
    else if (STAGE == 1) wA = wAll + tower * 589824 + 294912;
    else                 wA = wAll + 1179648 + tower * 147456;
    const uint4* __restrict__ wf4 = (const uint4*)(wA + (long)ocTile * 147456);
    const float* gamma = tower ? g_reg : g_cls;
    const float* beta  = tower ? be_reg : be_cls;
    const int meanBase = (tower * 3 + l) * 128 + n * 16;

    // halo slice staging (GN fused for STAGE>0, zero-pad after GN)
    auto stage = [&](int chunk, int hb, int lo, int hi) {
        const float* __restrict__ inC = inL + (long)chunk * 32 * HW;
        for (int i = lo + tid; i < hi; i += 256) {
            int w = i / 204; int px = i - w * 204;
            int ri = px / 34, ci = px - ri * 34;
            int ygl = y0 + ri - 1, xgl = x0 + ci - 1;
            float v0 = 0.f, v1 = 0.f;
            if ((unsigned)ygl < (unsigned)H && (unsigned)xgl < (unsigned)W) {
                long bidx = (long)(2 * w) * HW + (long)ygl * W + xgl;
                v0 = inC[bidx];
                v1 = inC[bidx + HW];
                if (STAGE > 0) {
                    int c = chunk * 32 + 2 * w;
                    int sg = meanBase + (c >> 4);
                    float m = g_mean[sg], rs = g_rstd[sg];
                    v0 = fmaxf((v0 - m) * rs * gamma[c]     + beta[c],     0.f);
                    v1 = fmaxf((v1 - m) * rs * gamma[c + 1] + beta[c + 1], 0.f);
                }
            }
            __half2 h = __floats2half2_rn(v0, v1);
            halo[hb][px * 20 + w] = *(uint32_t*)&h;
        }
    };

    // ---- prologue ----
    stage(0, 0, 0, 3264);
    uint4 Ac[4];
    if (active) {
#pragma unroll
        for (int q = 0; q < 4; ++q)
            Ac[q] = wf4[(q >> 1) * 256 + (wm * 2 + (q & 1)) * 32 + lane];
    }
    __syncthreads();

    for (int chunk = 0; chunk < 8; ++chunk) {
        const int hb = chunk & 1;
        const uint32_t hoff = (uint32_t)hb * 16320u;
        for (int tap = 0; tap < 9; ++tap) {
            const int cid = chunk * 9 + tap;
            uint4 An[4];
            if (active && cid < 71) {
                const uint4* wf = wf4 + (long)(cid + 1) * 512;
#pragma unroll
                for (int q = 0; q < 4; ++q)
                    An[q] = wf[(q >> 1) * 256 + (wm * 2 + (q & 1)) * 32 + lane];
            }
            if (active) {
                const uint32_t toff = hoff + (uint32_t)(((tap / 3) * 34 + (tap % 3)) * 80);
#pragma unroll
                for (int ks = 0; ks < 2; ++ks) {
                    const uint32_t o2 = toff + ks * 32;
#pragma unroll
                    for (int p = 0; p < 4; ++p) {
                        uint32_t b[4];
                        ldsm4(b, bAddr[p] + o2);
                        mma16(acc[0][2 * p],     (const uint32_t*)&Ac[ks * 2],     b[0], b[1]);
                        mma16(acc[1][2 * p],     (const uint32_t*)&Ac[ks * 2 + 1], b[0], b[1]);
                        mma16(acc[0][2 * p + 1], (const uint32_t*)&Ac[ks * 2],     b[2], b[3]);
                        mma16(acc[1][2 * p + 1], (const uint32_t*)&Ac[ks * 2 + 1], b[2], b[3]);
                    }
                }
            }
            if (chunk < 7) {
                int lo = tap * 368;
                int hi = lo + 368; if (hi > 3264) hi = 3264;
                stage(chunk + 1, hb ^ 1, lo, hi);
            }
            if (active && cid < 71) {
                Ac[0] = An[0]; Ac[1] = An[1]; Ac[2] = An[2]; Ac[3] = An[3];
            }
        }
        __syncthreads();
    }

    if (!active) return;

    // ---- epilogue ----
#pragma unroll
    for (int mbi = 0; mbi < 2; ++mbi) {
        const int ocl = (wm * 2 + mbi) * 16 + g;
        const int oc = ocBase + ocl;
        if (STAGE < 2) {
            float* outBase = (tower ? out_reg : out_cls) + SOFF[l];
            const float* bias = tower ? b_reg : b_cls;
            const float bv0 = bias[oc], bv1 = bias[oc + 8];
            float* o0 = outBase + ((long)n * 256 + oc) * HW;
#pragma unroll
            for (int nb = 0; nb < 8; ++nb) {
                int pxl = wn * 64 + nb * 8 + 2 * t;
                int ygl = y0 + (pxl >> 5);
                if (ygl >= H) continue;
                long idx = (long)ygl * W + x0 + (pxl & 31);
                *(float2*)(o0 + idx) =
                    make_float2(acc[mbi][nb][0] + bv0, acc[mbi][nb][1] + bv0);
                *(float2*)(o0 + 8L * HW + idx) =
                    make_float2(acc[mbi][nb][2] + bv1, acc[mbi][nb][3] + bv1);
            }
        } else if (tower == 0) {   // cls head
            float* out = out_cls;
#pragma unroll
            for (int nb = 0; nb < 8; ++nb) {
                int pxl = wn * 64 + nb * 8 + 2 * t;
                int ygl = y0 + (pxl >> 5);
                if (ygl >= H) continue;
                int pxg = ygl * W + x0 + (pxl & 31);
                long b = ((long)n * NPIX + OOFF[l] + pxg) * 20;
                if (oc < 20) {
                    float bv = b_cls[oc];
                    out[b + oc]      = acc[mbi][nb][0] + bv;
                    out[b + 20 + oc] = acc[mbi][nb][1] + bv;
                }
                if (oc + 8 < 20) {
                    float bv = b_cls[oc + 8];
                    out[b + oc + 8]      = acc[mbi][nb][2] + bv;
                    out[b + 20 + oc + 8] = acc[mbi][nb][3] + bv;
                }
            }
        } else {                   // reg + ctr head
            float* out = out_reg;
#pragma unroll
            for (int nb = 0; nb < 8; ++nb) {
                int pxl = wn * 64 + nb * 8 + 2 * t;
                int ygl = y0 + (pxl >> 5);
                if (ygl >= H) continue;
                int pxg = ygl * W + x0 + (pxl & 31);
#pragma unroll
                for (int rrj = 0; rrj < 2; ++rrj) {
                    int ocr = oc + rrj * 8;
                    float v0 = acc[mbi][nb][rrj * 2 + 0];
                    float v1 = acc[mbi][nb][rrj * 2 + 1];
                    if (ocr < 4) {
                        float bv = b_reg[ocr];
                        long rb = REG_BASE + (long)n * 67200 + (long)(OOFF[l] + pxg) * 4 + ocr;
                        out[rb]     = fmaxf(v0 + bv, 0.f);
                        out[rb + 4] = fmaxf(v1 + bv, 0.f);
                    } else if (ocr == 4) {
                        float bv = b_ctr[0];
                        long cb = CTR_BASE + (long)n * NPIX + OOFF[l] + pxg;
                        out[cb]     = v0 + bv;
                        out[cb + 1] = v1 + bv;
                    }
                }
            }
        }
    }
}

// ---------------------------------------------------------------------------
// Weight reorders -> fragment-linear half2 (same layout as R7).
// ---------------------------------------------------------------------------
__device__ __forceinline__ void frag_decode(int d, int& r, int& chunk, int& tap,
                                            int& oc128, int& icp)
{
    int j = d & 3; int q = d >> 2;
    int lane = q & 31; q >>= 5;
    int mb = q & 7;  q >>= 3;
    int ks = q & 1;  q >>= 1;
    tap = q % 9; q /= 9;
    chunk = q & 7; q >>= 3;
    r = q;
    oc128 = mb * 16 + (lane >> 2) + (j & 1) * 8;
    icp   = chunk * 32 + ks * 16 + (lane & 3) * 2 + ((j >> 1) & 1) * 8;
}

__global__ void reorder_tower(const float* __restrict__ w, uint32_t* __restrict__ dst)
{
    int d = blockIdx.x * 256 + threadIdx.x;
    if (d >= 589824) return;
    int r, chunk, tap, oc128, icp;
    frag_decode(d, r, chunk, tap, oc128, icp);
    int layer = r >> 1;
    int oc = (r & 1) * 128 + oc128;
    const float* src = w + (long)layer * 589824;
    float v0 = src[((long)oc * 256 + icp) * 9 + tap];
    float v1 = src[((long)oc * 256 + icp + 1) * 9 + tap];
    __half2 h = __floats2half2_rn(v0, v1);
    dst[d] = *(uint32_t*)&h;
}

__global__ void reorder_heads(const float* __restrict__ wcls, const float* __restrict__ wreg,
                              const float* __restrict__ wctr, uint32_t* __restrict__ dst)
{
    int d = blockIdx.x * 256 + threadIdx.x;
    if (d >= 294912) return;
    int r, chunk, tap, oc128, icp;
    frag_decode(d, r, chunk, tap, oc128, icp);
    int oc = oc128;
    float v0 = 0.f, v1 = 0.f;
    if (r == 0) {
        if (oc < 20) {
            v0 = wcls[((long)oc * 256 + icp) * 9 + tap];
            v1 = wcls[((long)oc * 256 + icp + 1) * 9 + tap];
        }
    } else {
        if (oc < 4) {
            v0 = wreg[((long)oc * 256 + icp) * 9 + tap];
            v1 = wreg[((long)oc * 256 + icp + 1) * 9 + tap];
        } else if (oc == 4) {
            v0 = wctr[(long)icp * 9 + tap];
            v1 = wctr[(long)(icp + 1) * 9 + tap];
        }
    }
    __half2 h = __floats2half2_rn(v0, v1);
    dst[d] = *(uint32_t*)&h;
}

// ---------------------------------------------------------------------------
// GroupNorm stats for all (tower, level) pairs in one launch.
// grid = (128, 6): x -> (n, group), y -> tower*3 + level.
// ---------------------------------------------------------------------------
__global__ void gn_stats_all(const float* __restrict__ bufCls, const float* __restrict__ bufReg)
{
    const int by = blockIdx.y;
    const int tower = by / 3, l = by - tower * 3;
    const int HWs[3] = { 12800, 3200, 800 };
    const long SOFF[3] = { 0L, 26214400L, 32768000L };
    const int HW = HWs[l];
    const int n = blockIdx.x >> 4;
    const int g = blockIdx.x & 15;
    const float4* p = (const float4*)((tower ? bufReg : bufCls) + SOFF[l]
                                      + ((long)n * 256 + (long)g * 16) * HW);
    const int total4 = (16 * HW) >> 2;
    float s = 0.f, s2 = 0.f;
    for (int i = threadIdx.x; i < total4; i += blockDim.x) {
        float4 v = p[i];
        s  += v.x + v.y + v.z + v.w;
        s2 += v.x * v.x + v.y * v.y + v.z * v.z + v.w * v.w;
    }
    __shared__ float rs[8], rs2[8];
#pragma unroll
    for (int o = 16; o; o >>= 1) {
        s  += __shfl_xor_sync(~0u, s, o);
        s2 += __shfl_xor_sync(~0u, s2, o);
    }
    const int w = threadIdx.x >> 5, lid = threadIdx.x & 31;
    if (lid == 0) { rs[w] = s; rs2[w] = s2; }
    __syncthreads();
    if (w == 0) {
        s  = (lid < 8) ? rs[lid]  : 0.f;
        s2 = (lid < 8) ? rs2[lid] : 0.f;
#pragma unroll
        for (int o = 4; o; o >>= 1) {
            s  += __shfl_xor_sync(~0u, s, o);
            s2 += __shfl_xor_sync(~0u, s2, o);
        }
        if (lid == 0) {
            float inv = 1.f / (float)(16 * HW);
            float m = s * inv;
            g_mean[by * 128 + blockIdx.x] = m;
            g_rstd[by * 128 + blockIdx.x] = rsqrtf(s2 * inv - m * m + 1e-5f);
        }
    }
}

// ---------------------------------------------------------------------------
extern "C" void kernel_launch(void* const* d_in, const int* in_sizes, int n_in,
                              void* d_out, int out_size)
{
    (void)in_sizes; (void)n_in; (void)out_size;
    const float* feat0 = (const float*)d_in[0];
    const float* feat1 = (const float*)d_in[1];
    const float* feat2 = (const float*)d_in[2];
    const float* cls_conv_w = (const float*)d_in[3];
    const float* cls_conv_b = (const float*)d_in[4];
    const float* cls_gn_g = (const float*)d_in[5];
    const float* cls_gn_b = (const float*)d_in[6];
    const float* cls_out_w = (const float*)d_in[7];
    const float* cls_out_b = (const float*)d_in[8];
    const float* reg_conv_w = (const float*)d_in[9];
    const float* reg_conv_b = (const float*)d_in[10];
    const float* reg_gn_g = (const float*)d_in[11];
    const float* reg_gn_b = (const float*)d_in[12];
    const float* reg_out_w = (const float*)d_in[13];
    const float* reg_out_b = (const float*)d_in[14];
    const float* ctr_w = (const float*)d_in[15];
    const float* ctr_b = (const float*)d_in[16];
    float* out = (float*)d_out;

    float *pA, *pB, *pC, *pD;
    uint32_t* pW;
    cudaGetSymbolAddress((void**)&pA, g_A);
    cudaGetSymbolAddress((void**)&pB, g_B);
    cudaGetSymbolAddress((void**)&pC, g_C);
    cudaGetSymbolAddress((void**)&pD, g_D);
    cudaGetSymbolAddress((void**)&pW, g_W);

    // weight reorders
    reorder_tower<<<2304, 256>>>(cls_conv_w, pW);
    reorder_tower<<<2304, 256>>>(reg_conv_w, pW + 589824);
    reorder_heads<<<1152, 256>>>(cls_out_w, reg_out_w, ctr_w, pW + 1179648);

    // stage 1: conv1 (both towers, all levels)
    conv_mma<0><<<dim3(133, 4, 8), 256>>>(feat0, feat1, feat2, pW,
                                          cls_conv_b, reg_conv_b, nullptr,
                                          nullptr, nullptr, nullptr, nullptr,
                                          pA, pC);
    gn_stats_all<<<dim3(128, 6), 256>>>(pA, pC);

    // stage 2: conv2 (GN layer0 fused)
    conv_mma<1><<<dim3(133, 4, 8), 256>>>(pA, pC, nullptr, pW,
                                          cls_conv_b + 256, reg_conv_b + 256, nullptr,
                                          cls_gn_g, cls_gn_b, reg_gn_g, reg_gn_b,
                                          pB, pD);
    gn_stats_all<<<dim3(128, 6), 256>>>(pB, pD);

    // stage 3: heads (GN layer1 fused)
    conv_mma<2><<<dim3(133, 2, 8), 256>>>(pB, pD, nullptr, pW,
                                          cls_out_b, reg_out_b, ctr_b,
                                          cls_gn_g + 256, cls_gn_b + 256,
                                          reg_gn_g + 256, reg_gn_b + 256,
                                          out, out);
}

// round 9
// speedup vs baseline: 10.6664x; 1.0178x over previous
#include <cuda_runtime.h>
#include <cuda_fp16.h>
#include <stdint.h>

#define NPIX 16800
#define REG_BASE 2688000L
#define CTR_BASE 3225600L

// static device scratch (no cudaMalloc anywhere). Per-level regions inside
// each buffer: level l at SOFF[l], size 8*256*HW_l floats.
#define BUF_FLOATS 34406400L
__device__ float    g_A[BUF_FLOATS];   // cls conv1 out
__device__ float    g_B[BUF_FLOATS];   // cls conv2 out
__device__ float    g_C[BUF_FLOATS];   // reg conv1 out
__device__ float    g_D[BUF_FLOATS];   // reg conv2 out
__device__ uint32_t g_W[1474560];      // fragment-ordered half2 weights
__device__ float    g_mean[768];       // [tower*3+level][n*16+g]
__device__ float    g_rstd[768];

__device__ __forceinline__ uint32_t smem_u32(const void* p) {
    uint32_t a;
    asm("{ .reg .u64 t; cvta.to.shared.u64 t, %1; cvt.u32.u64 %0, t; }" : "=r"(a) : "l"(p));
    return a;
}
__device__ __forceinline__ void mma16(float* c, const uint32_t* a, uint32_t b0, uint32_t b1) {
    asm volatile(
        "mma.sync.aligned.m16n8k16.row.col.f32.f16.f16.f32 "
        "{%0,%1,%2,%3}, {%4,%5,%6,%7}, {%8,%9}, {%0,%1,%2,%3};"
        : "+f"(c[0]), "+f"(c[1]), "+f"(c[2]), "+f"(c[3])
        : "r"(a[0]), "r"(a[1]), "r"(a[2]), "r"(a[3]), "r"(b0), "r"(b1));
}
__device__ __forceinline__ void ldsm4(uint32_t* r, uint32_t addr) {
    asm volatile("ldmatrix.sync.aligned.m8n8.x4.shared.b16 {%0,%1,%2,%3}, [%4];"
        : "=r"(r[0]), "=r"(r[1]), "=r"(r[2]), "=r"(r[3]) : "r"(addr));
}

// ---------------------------------------------------------------------------
// Merged fp16 mma.sync conv3x3 s1p1 (NCHW), all levels x both towers per
// stage launch. R9: halo staging is LATENCY-PIPELINED — per tap the <=2
// staging LDGs issue BEFORE the MMA block (into registers) and the
// GN+pack+STS happens AFTER it, so global latency hides behind tensor work.
//  STAGE 0: conv1 (no GN), feats -> A/C
//  STAGE 1: conv2 (GN layer0 fused), A/C -> B/D
//  STAGE 2: heads (GN layer1 fused), B/D -> final output
// ---------------------------------------------------------------------------
template<int STAGE>
__global__ __launch_bounds__(256, 2)
void conv_mma(const float* __restrict__ f0, const float* __restrict__ f1,
              const float* __restrict__ f2, const uint32_t* __restrict__ wAll,
              const float* __restrict__ b_cls, const float* __restrict__ b_reg,
              const float* __restrict__ b_ctr,
              const float* __restrict__ g_cls, const float* __restrict__ be_cls,
              const float* __restrict__ g_reg, const float* __restrict__ be_reg,
              float* __restrict__ out_cls, float* __restrict__ out_reg)
{
    // ---- level decode ----
    const int bx = blockIdx.x;
    int l, tile, H, W, wt;
    if (bx < 100)      { l = 0; tile = bx;       H = 100; W = 128; wt = 4; }
    else if (bx < 126) { l = 1; tile = bx - 100; H = 50;  W = 64;  wt = 2; }
    else               { l = 2; tile = bx - 126; H = 25;  W = 32;  wt = 1; }
    const int HW = H * W;
    const long SOFF[3]  = { 0L, 26214400L, 32768000L };
    const int  OOFF[3]  = { 0, 12800, 16000 };

    // ---- tower / oc-tile decode ----
    int tower, ocTile;
    if (STAGE == 2) { tower = blockIdx.y; ocTile = 0; }
    else            { tower = blockIdx.y >> 1; ocTile = blockIdx.y & 1; }
    const int OCv = (STAGE == 2) ? (tower ? 5 : 20) : 256;

    const int tid = threadIdx.x, wid = tid >> 5, lane = tid & 31;
    const int g = lane >> 2, t = lane & 3;
    const int wm = wid & 3, wn = wid >> 2;
    const int n = blockIdx.z;
    const int ocBase = ocTile * 128;
    const int x0 = (tile % wt) << 5;
    const int y0 = (tile / wt) << 2;
    const bool active = (ocBase + wm * 32) < OCv;

    __shared__ uint32_t halo[2][4080];   // 204 px * 20 words, double-buffered

    // ldmatrix per-lane base addresses
    const int mm = lane >> 3, rr = lane & 7;
    const uint32_t sbase = smem_u32(halo);
    uint32_t bAddr[4];
#pragma unroll
    for (int p = 0; p < 4; ++p) {
        int pxl = wn * 64 + (2 * p + (mm >> 1)) * 8 + rr;
        bAddr[p] = sbase + (uint32_t)((((pxl >> 5) * 34 + (pxl & 31)) * 20 + (mm & 1) * 4) * 4);
    }

    float acc[2][8][4];
#pragma unroll
    for (int i = 0; i < 2; ++i)
#pragma unroll
        for (int j = 0; j < 8; ++j)
#pragma unroll
            for (int q = 0; q < 4; ++q) acc[i][j][q] = 0.f;

    // ---- input / weight / GN pointers ----
    const float* inL;
    if (STAGE == 0) inL = ((l == 0) ? f0 : (l == 1) ? f1 : f2) + (long)n * 256 * HW;
    else            inL = (tower ? f1 : f0) + SOFF[l] + (long)n * 256 * HW;
    const uint32_t* wA;
    if (STAGE == 0)      wA = wAll + tower * 589824;
    else if (STAGE == 1) wA = wAll + tower * 589824 + 294912;
    else                 wA = wAll + 1179648 + tower * 147456;
    const uint4* __restrict__ wf4 = (const uint4*)(wA + (long)ocTile * 147456);
    const float* gamma = tower ? g_reg : g_cls;
    const float* beta  = tower ? be_reg : be_cls;
    const int meanBase = (tower * 3 + l) * 128 + n * 16;

    // raw load of one staging item (no math; predicated)
    auto stage_ld = [&](int chunk, int i, float& v0, float& v1) {
        int w = i / 204; int px = i - w * 204;
        int ri = px / 34, ci = px - ri * 34;
        int ygl = y0 + ri - 1, xgl = x0 + ci - 1;
        v0 = 0.f; v1 = 0.f;
        if ((unsigned)ygl < (unsigned)H && (unsigned)xgl < (unsigned)W) {
            const float* inC = inL + (long)chunk * 32 * HW;
            long bidx = (long)(2 * w) * HW + (long)ygl * W + xgl;
            v0 = inC[bidx];
            v1 = inC[bidx + HW];
        }
    };
    // GN + pack + STS of one staging item
    auto stage_st = [&](int chunk, int hb, int i, float v0, float v1) {
        int w = i / 204; int px = i - w * 204;
        if (STAGE > 0) {
            int ri = px / 34, ci = px - ri * 34;
            int ygl = y0 + ri - 1, xgl = x0 + ci - 1;
            if ((unsigned)ygl < (unsigned)H && (unsigned)xgl < (unsigned)W) {
                int c = chunk * 32 + 2 * w;
                int sg = meanBase + (c >> 4);
                float m = g_mean[sg], rs = g_rstd[sg];
                v0 = fmaxf((v0 - m) * rs * gamma[c]     + beta[c],     0.f);
                v1 = fmaxf((v1 - m) * rs * gamma[c + 1] + beta[c + 1], 0.f);
            }
        }
        __half2 h = __floats2half2_rn(v0, v1);
        halo[hb][px * 20 + w] = *(uint32_t*)&h;
    };

    // ---- prologue: chunk-0 halo (immediate), tap-0 A fragments ----
    for (int i = tid; i < 3264; i += 256) {
        float v0, v1;
        stage_ld(0, i, v0, v1);
        stage_st(0, 0, i, v0, v1);
    }
    uint4 Ac[4];
    if (active) {
#pragma unroll
        for (int q = 0; q < 4; ++q)
            Ac[q] = wf4[(q >> 1) * 256 + (wm * 2 + (q & 1)) * 32 + lane];
    }
    __syncthreads();

    for (int chunk = 0; chunk < 8; ++chunk) {
        const int hb = chunk & 1;
        const uint32_t hoff = (uint32_t)hb * 16320u;
        for (int tap = 0; tap < 9; ++tap) {
            const int cid = chunk * 9 + tap;

            // ---- staging LOAD phase: issue global loads early ----
            float s0a = 0.f, s1a = 0.f, s0b = 0.f, s1b = 0.f;
            int i0 = -1, i1 = -1;
            if (chunk < 7) {
                int lo = tap * 368;
                int hi = lo + 368; if (hi > 3264) hi = 3264;
                int ia = lo + tid;
                if (ia < hi) { i0 = ia; stage_ld(chunk + 1, ia, s0a, s1a); }
                int ib = ia + 256;
                if (ib < hi) { i1 = ib; stage_ld(chunk + 1, ib, s0b, s1b); }
            }
            // ---- A prefetch for next tap ----
            uint4 An[4];
            if (active && cid < 71) {
                const uint4* wf = wf4 + (long)(cid + 1) * 512;
#pragma unroll
                for (int q = 0; q < 4; ++q)
                    An[q] = wf[(q >> 1) * 256 + (wm * 2 + (q & 1)) * 32 + lane];
            }
            // ---- MMA block (latency-hiding window) ----
            if (active) {
                const uint32_t toff = hoff + (uint32_t)(((tap / 3) * 34 + (tap % 3)) * 80);
#pragma unroll
                for (int ks = 0; ks < 2; ++ks) {
                    const uint32_t o2 = toff + ks * 32;
#pragma unroll
                    for (int p = 0; p < 4; ++p) {
                        uint32_t b[4];
                        ldsm4(b, bAddr[p] + o2);
                        mma16(acc[0][2 * p],     (const uint32_t*)&Ac[ks * 2],     b[0], b[1]);
                        mma16(acc[1][2 * p],     (const uint32_t*)&Ac[ks * 2 + 1], b[0], b[1]);
                        mma16(acc[0][2 * p + 1], (const uint32_t*)&Ac[ks * 2],     b[2], b[3]);
                        mma16(acc[1][2 * p + 1], (const uint32_t*)&Ac[ks * 2 + 1], b[2], b[3]);
                    }
                }
            }
            // ---- staging STORE phase: data arrived during MMAs ----
            if (i0 >= 0) stage_st(chunk + 1, hb ^ 1, i0, s0a, s1a);
            if (i1 >= 0) stage_st(chunk + 1, hb ^ 1, i1, s0b, s1b);
            if (active && cid < 71) {
                Ac[0] = An[0]; Ac[1] = An[1]; Ac[2] = An[2]; Ac[3] = An[3];
            }
        }
        __syncthreads();
    }

    if (!active) return;

    // ---- epilogue ----
#pragma unroll
    for (int mbi = 0; mbi < 2; ++mbi) {
        const int ocl = (wm * 2 + mbi) * 16 + g;
        const int oc = ocBase + ocl;
        if (STAGE < 2) {
            float* outBase = (tower ? out_reg : out_cls) + SOFF[l];
            const float* bias = tower ? b_reg : b_cls;
            const float bv0 = bias[oc], bv1 = bias[oc + 8];
            float* o0 = outBase + ((long)n * 256 + oc) * HW;
#pragma unroll
            for (int nb = 0; nb < 8; ++nb) {
                int pxl = wn * 64 + nb * 8 + 2 * t;
                int ygl = y0 + (pxl >> 5);
                if (ygl >= H) continue;
                long idx = (long)ygl * W + x0 + (pxl & 31);
                *(float2*)(o0 + idx) =
                    make_float2(acc[mbi][nb][0] + bv0, acc[mbi][nb][1] + bv0);
                *(float2*)(o0 + 8L * HW + idx) =
                    make_float2(acc[mbi][nb][2] + bv1, acc[mbi][nb][3] + bv1);
            }
        } else if (tower == 0) {   // cls head
            float* out = out_cls;
#pragma unroll
            for (int nb = 0; nb < 8; ++nb) {
                int pxl = wn * 64 + nb * 8 + 2 * t;
                int ygl = y0 + (pxl >> 5);
                if (ygl >= H) continue;
                int pxg = ygl * W + x0 + (pxl & 31);
                long b = ((long)n * NPIX + OOFF[l] + pxg) * 20;
                if (oc < 20) {
                    float bv = b_cls[oc];
                    out[b + oc]      = acc[mbi][nb][0] + bv;
                    out[b + 20 + oc] = acc[mbi][nb][1] + bv;
                }
                if (oc + 8 < 20) {
                    float bv = b_cls[oc + 8];
                    out[b + oc + 8]      = acc[mbi][nb][2] + bv;
                    out[b + 20 + oc + 8] = acc[mbi][nb][3] + bv;
                }
            }
        } else {                   // reg + ctr head
            float* out = out_reg;
#pragma unroll
            for (int nb = 0; nb < 8; ++nb) {
                int pxl = wn * 64 + nb * 8 + 2 * t;
                int ygl = y0 + (pxl >> 5);
                if (ygl >= H) continue;
                int pxg = ygl * W + x0 + (pxl & 31);
#pragma unroll
                for (int rrj = 0; rrj < 2; ++rrj) {
                    int ocr = oc + rrj * 8;
                    float v0 = acc[mbi][nb][rrj * 2 + 0];
                    float v1 = acc[mbi][nb][rrj * 2 + 1];
                    if (ocr < 4) {
                        float bv = b_reg[ocr];
                        long rb = REG_BASE + (long)n * 67200 + (long)(OOFF[l] + pxg) * 4 + ocr;
                        out[rb]     = fmaxf(v0 + bv, 0.f);
                        out[rb + 4] = fmaxf(v1 + bv, 0.f);
                    } else if (ocr == 4) {
                        float bv = b_ctr[0];
                        long cb = CTR_BASE + (long)n * NPIX + OOFF[l] + pxg;
                        out[cb]     = v0 + bv;
                        out[cb + 1] = v1 + bv;
                    }
                }
            }
        }
    }
}

// ---------------------------------------------------------------------------
// Weight reorders -> fragment-linear half2 (unchanged layout).
// ---------------------------------------------------------------------------
__device__ __forceinline__ void frag_decode(int d, int& r, int& chunk, int& tap,
                                            int& oc128, int& icp)
{
    int j = d & 3; int q = d >> 2;
    int lane = q & 31; q >>= 5;
    int mb = q & 7;  q >>= 3;
    int ks = q & 1;  q >>= 1;
    tap = q % 9; q /= 9;
    chunk = q & 7; q >>= 3;
    r = q;
    oc128 = mb * 16 + (lane >> 2) + (j & 1) * 8;
    icp   = chunk * 32 + ks * 16 + (lane & 3) * 2 + ((j >> 1) & 1) * 8;
}

__global__ void reorder_tower(const float* __restrict__ w, uint32_t* __restrict__ dst)
{
    int d = blockIdx.x * 256 + threadIdx.x;
    if (d >= 589824) return;
    int r, chunk, tap, oc128, icp;
    frag_decode(d, r, chunk, tap, oc128, icp);
    int layer = r >> 1;
    int oc = (r & 1) * 128 + oc128;
    const float* src = w + (long)layer * 589824;
    float v0 = src[((long)oc * 256 + icp) * 9 + tap];
    float v1 = src[((long)oc * 256 + icp + 1) * 9 + tap];
    __half2 h = __floats2half2_rn(v0, v1);
    dst[d] = *(uint32_t*)&h;
}

__global__ void reorder_heads(const float* __restrict__ wcls, const float* __restrict__ wreg,
                              const float* __restrict__ wctr, uint32_t* __restrict__ dst)
{
    int d = blockIdx.x * 256 + threadIdx.x;
    if (d >= 294912) return;
    int r, chunk, tap, oc128, icp;
    frag_decode(d, r, chunk, tap, oc128, icp);
    int oc = oc128;
    float v0 = 0.f, v1 = 0.f;
    if (r == 0) {
        if (oc < 20) {
            v0 = wcls[((long)oc * 256 + icp) * 9 + tap];
            v1 = wcls[((long)oc * 256 + icp + 1) * 9 + tap];
        }
    } else {
        if (oc < 4) {
            v0 = wreg[((long)oc * 256 + icp) * 9 + tap];
            v1 = wreg[((long)oc * 256 + icp + 1) * 9 + tap];
        } else if (oc == 4) {
            v0 = wctr[(long)icp * 9 + tap];
            v1 = wctr[(long)(icp + 1) * 9 + tap];
        }
    }
    __half2 h = __floats2half2_rn(v0, v1);
    dst[d] = *(uint32_t*)&h;
}

// ---------------------------------------------------------------------------
// GroupNorm stats for all (tower, level) pairs in one launch.
// ---------------------------------------------------------------------------
__global__ void gn_stats_all(const float* __restrict__ bufCls, const float* __restrict__ bufReg)
{
    const int by = blockIdx.y;
    const int tower = by / 3, l = by - tower * 3;
    const int HWs[3] = { 12800, 3200, 800 };
    const long SOFF[3] = { 0L, 26214400L, 32768000L };
    const int HW = HWs[l];
    const int n = blockIdx.x >> 4;
    const int g = blockIdx.x & 15;
    const float4* p = (const float4*)((tower ? bufReg : bufCls) + SOFF[l]
                                      + ((long)n * 256 + (long)g * 16) * HW);
    const int total4 = (16 * HW) >> 2;
    float s = 0.f, s2 = 0.f;
    for (int i = threadIdx.x; i < total4; i += blockDim.x) {
        float4 v = p[i];
        s  += v.x + v.y + v.z + v.w;
        s2 += v.x * v.x + v.y * v.y + v.z * v.z + v.w * v.w;
    }
    __shared__ float rs[8], rs2[8];
#pragma unroll
    for (int o = 16; o; o >>= 1) {
        s  += __shfl_xor_sync(~0u, s, o);
        s2 += __shfl_xor_sync(~0u, s2, o);
    }
    const int w = threadIdx.x >> 5, lid = threadIdx.x & 31;
    if (lid == 0) { rs[w] = s; rs2[w] = s2; }
    __syncthreads();
    if (w == 0) {
        s  = (lid < 8) ? rs[lid]  : 0.f;
        s2 = (lid < 8) ? rs2[lid] : 0.f;
#pragma unroll
        for (int o = 4; o; o >>= 1) {
            s  += __shfl_xor_sync(~0u, s, o);
            s2 += __shfl_xor_sync(~0u, s2, o);
        }
        if (lid == 0) {
            float inv = 1.f / (float)(16 * HW);
            float m = s * inv;
            g_mean[by * 128 + blockIdx.x] = m;
            g_rstd[by * 128 + blockIdx.x] = rsqrtf(s2 * inv - m * m + 1e-5f);
        }
    }
}

// ---------------------------------------------------------------------------
extern "C" void kernel_launch(void* const* d_in, const int* in_sizes, int n_in,
                              void* d_out, int out_size)
{
    (void)in_sizes; (void)n_in; (void)out_size;
    const float* feat0 = (const float*)d_in[0];
    const float* feat1 = (const float*)d_in[1];
    const float* feat2 = (const float*)d_in[2];
    const float* cls_conv_w = (const float*)d_in[3];
    const float* cls_conv_b = (const float*)d_in[4];
    const float* cls_gn_g = (const float*)d_in[5];
    const float* cls_gn_b = (const float*)d_in[6];
    const float* cls_out_w = (const float*)d_in[7];
    const float* cls_out_b = (const float*)d_in[8];
    const float* reg_conv_w = (const float*)d_in[9];
    const float* reg_conv_b = (const float*)d_in[10];
    const float* reg_gn_g = (const float*)d_in[11];
    const float* reg_gn_b = (const float*)d_in[12];
    const float* reg_out_w = (const float*)d_in[13];
    const float* reg_out_b = (const float*)d_in[14];
    const float* ctr_w = (const float*)d_in[15];
    const float* ctr_b = (const float*)d_in[16];
    float* out = (float*)d_out;

    float *pA, *pB, *pC, *pD;
    uint32_t* pW;
    cudaGetSymbolAddress((void**)&pA, g_A);
    cudaGetSymbolAddress((void**)&pB, g_B);
    cudaGetSymbolAddress((void**)&pC, g_C);
    cudaGetSymbolAddress((void**)&pD, g_D);
    cudaGetSymbolAddress((void**)&pW, g_W);

    // weight reorders
    reorder_tower<<<2304, 256>>>(cls_conv_w, pW);
    reorder_tower<<<2304, 256>>>(reg_conv_w, pW + 589824);
    reorder_heads<<<1152, 256>>>(cls_out_w, reg_out_w, ctr_w, pW + 1179648);

    // stage 1: conv1 (both towers, all levels)
    conv_mma<0><<<dim3(133, 4, 8), 256>>>(feat0, feat1, feat2, pW,
                                          cls_conv_b, reg_conv_b, nullptr,
                                          nullptr, nullptr, nullptr, nullptr,
                                          pA, pC);
    gn_stats_all<<<dim3(128, 6), 256>>>(pA, pC);

    // stage 2: conv2 (GN layer0 fused)
    conv_mma<1><<<dim3(133, 4, 8), 256>>>(pA, pC, nullptr, pW,
                                          cls_conv_b + 256, reg_conv_b + 256, nullptr,
                                          cls_gn_g, cls_gn_b, reg_gn_g, reg_gn_b,
                                          pB, pD);
    gn_stats_all<<<dim3(128, 6), 256>>>(pB, pD);

    // stage 3: heads (GN layer1 fused)
    conv_mma<2><<<dim3(133, 2, 8), 256>>>(pB, pD, nullptr, pW,
                                          cls_out_b, reg_out_b, ctr_b,
                                          cls_gn_g + 256, cls_gn_b + 256,
                                          reg_gn_g + 256, reg_gn_b + 256,
                                          out, out);
}

// round 10
// speedup vs baseline: 12.0522x; 1.1299x over previous
#include <cuda_runtime.h>
#include <cuda_fp16.h>
#include <stdint.h>

#define NPIX 16800
#define REG_BASE 2688000L
#define CTR_BASE 3225600L

// static device scratch (no cudaMalloc anywhere). Per-level regions inside
// each buffer: level l at SOFF[l], size 8*256*HW_l floats.
#define BUF_FLOATS 34406400L
__device__ float    g_A[BUF_FLOATS];   // cls conv1 out
__device__ float    g_B[BUF_FLOATS];   // cls conv2 out
__device__ float    g_C[BUF_FLOATS];   // reg conv1 out
__device__ float    g_D[BUF_FLOATS];   // reg conv2 out
__device__ uint32_t g_W[1474560];      // fragment-ordered half2 weights
__device__ float    g_mean[768];       // [tower*3+level][n*16+g]
__device__ float    g_rstd[768];

__device__ __forceinline__ uint32_t smem_u32(const void* p) {
    uint32_t a;
    asm("{ .reg .u64 t; cvta.to.shared.u64 t, %1; cvt.u32.u64 %0, t; }" : "=r"(a) : "l"(p));
    return a;
}
__device__ __forceinline__ void mma16(float* c, const uint32_t* a, uint32_t b0, uint32_t b1) {
    asm volatile(
        "mma.sync.aligned.m16n8k16.row.col.f32.f16.f16.f32 "
        "{%0,%1,%2,%3}, {%4,%5,%6,%7}, {%8,%9}, {%0,%1,%2,%3};"
        : "+f"(c[0]), "+f"(c[1]), "+f"(c[2]), "+f"(c[3])
        : "r"(a[0]), "r"(a[1]), "r"(a[2]), "r"(a[3]), "r"(b0), "r"(b1));
}
__device__ __forceinline__ void ldsm4(uint32_t* r, uint32_t addr) {
    asm volatile("ldmatrix.sync.aligned.m8n8.x4.shared.b16 {%0,%1,%2,%3}, [%4];"
        : "=r"(r[0]), "=r"(r[1]), "=r"(r[2]), "=r"(r[3]) : "r"(addr));
}

// ---------------------------------------------------------------------------
// Merged fp16 mma.sync conv3x3 s1p1 (NCHW). R10: for tower stages both
// oc-tiles live in ONE 512-thread CTA (warp>>3 = ocTile) so the halo is
// staged/loaded ONCE per (pixel tile, tower) instead of twice. Staging stays
// latency-pipelined (LDG before MMA block, GN+STS after). Heads keep the
// 256-thread shape.
//  STAGE 0: conv1 (no GN), feats -> A/C
//  STAGE 1: conv2 (GN layer0 fused), A/C -> B/D
//  STAGE 2: heads (GN layer1 fused), B/D -> final output
// ---------------------------------------------------------------------------
template<int STAGE, int NW>
__global__ __launch_bounds__(NW * 32, NW == 8 ? 2 : 1)
void conv_mma(const float* __restrict__ f0, const float* __restrict__ f1,
              const float* __restrict__ f2, const uint32_t* __restrict__ wAll,
              const float* __restrict__ b_cls, const float* __restrict__ b_reg,
              const float* __restrict__ b_ctr,
              const float* __restrict__ g_cls, const float* __restrict__ be_cls,
              const float* __restrict__ g_reg, const float* __restrict__ be_reg,
              float* __restrict__ out_cls, float* __restrict__ out_reg)
{
    constexpr int THREADS = NW * 32;
    // ---- level decode ----
    const int bx = blockIdx.x;
    int l, tile, H, W, wt;
    if (bx < 100)      { l = 0; tile = bx;       H = 100; W = 128; wt = 4; }
    else if (bx < 126) { l = 1; tile = bx - 100; H = 50;  W = 64;  wt = 2; }
    else               { l = 2; tile = bx - 126; H = 25;  W = 32;  wt = 1; }
    const int HW = H * W;
    const long SOFF[3]  = { 0L, 26214400L, 32768000L };
    const int  OOFF[3]  = { 0, 12800, 16000 };

    const int tid = threadIdx.x, wid = tid >> 5, lane = tid & 31;
    const int iw = wid & 7;                 // warp index within oc-tile group
    const int g = lane >> 2, t = lane & 3;
    const int wm = iw & 3, wn = iw >> 2;
    const int n = blockIdx.z;

    // ---- tower / oc-tile decode ----
    const int tower  = blockIdx.y;
    const int ocTile = (NW == 16) ? (wid >> 3) : 0;
    const int OCv = (STAGE == 2) ? (tower ? 5 : 20) : 256;
    const int ocBase = ocTile * 128;
    const int x0 = (tile % wt) << 5;
    const int y0 = (tile / wt) << 2;
    const bool active = (ocBase + wm * 32) < OCv;

    __shared__ uint32_t halo[2][4080];   // 204 px * 20 words, double-buffered

    // ldmatrix per-lane base addresses
    const int mm = lane >> 3, rr = lane & 7;
    const uint32_t sbase = smem_u32(halo);
    uint32_t bAddr[4];
#pragma unroll
    for (int p = 0; p < 4; ++p) {
        int pxl = wn * 64 + (2 * p + (mm >> 1)) * 8 + rr;
        bAddr[p] = sbase + (uint32_t)((((pxl >> 5) * 34 + (pxl & 31)) * 20 + (mm & 1) * 4) * 4);
    }

    float acc[2][8][4];
#pragma unroll
    for (int i = 0; i < 2; ++i)
#pragma unroll
        for (int j = 0; j < 8; ++j)
#pragma unroll
            for (int q = 0; q < 4; ++q) acc[i][j][q] = 0.f;

    // ---- input / weight / GN pointers ----
    const float* inL;
    if (STAGE == 0) inL = ((l == 0) ? f0 : (l == 1) ? f1 : f2) + (long)n * 256 * HW;
    else            inL = (tower ? f1 : f0) + SOFF[l] + (long)n * 256 * HW;
    const uint32_t* wA;
    if (STAGE == 0)      wA = wAll + tower * 589824;
    else if (STAGE == 1) wA = wAll + tower * 589824 + 294912;
    else                 wA = wAll + 1179648 + tower * 147456;
    const uint4* __restrict__ wf4 = (const uint4*)(wA + (long)ocTile * 147456);
    const float* gamma = tower ? g_reg : g_cls;
    const float* beta  = tower ? be_reg : be_cls;
    const int meanBase = (tower * 3 + l) * 128 + n * 16;

    // raw load of one staging item (no math; predicated)
    auto stage_ld = [&](int chunk, int i, float& v0, float& v1) {
        int w = i / 204; int px = i - w * 204;
        int ri = px / 34, ci = px - ri * 34;
        int ygl = y0 + ri - 1, xgl = x0 + ci - 1;
        v0 = 0.f; v1 = 0.f;
        if ((unsigned)ygl < (unsigned)H && (unsigned)xgl < (unsigned)W) {
            const float* inC = inL + (long)chunk * 32 * HW;
            long bidx = (long)(2 * w) * HW + (long)ygl * W + xgl;
            v0 = inC[bidx];
            v1 = inC[bidx + HW];
        }
    };
    // GN + pack + STS of one staging item
    auto stage_st = [&](int chunk, int hb, int i, float v0, float v1) {
        int w = i / 204; int px = i - w * 204;
        if (STAGE > 0) {
            int ri = px / 34, ci = px - ri * 34;
            int ygl = y0 + ri - 1, xgl = x0 + ci - 1;
            if ((unsigned)ygl < (unsigned)H && (unsigned)xgl < (unsigned)W) {
                int c = chunk * 32 + 2 * w;
                int sg = meanBase + (c >> 4);
                float m = g_mean[sg], rs = g_rstd[sg];
                v0 = fmaxf((v0 - m) * rs * gamma[c]     + beta[c],     0.f);
                v1 = fmaxf((v1 - m) * rs * gamma[c + 1] + beta[c + 1], 0.f);
            }
        }
        __half2 h = __floats2half2_rn(v0, v1);
        halo[hb][px * 20 + w] = *(uint32_t*)&h;
    };

    // ---- prologue: chunk-0 halo (immediate), tap-0 A fragments ----
    for (int i = tid; i < 3264; i += THREADS) {
        float v0, v1;
        stage_ld(0, i, v0, v1);
        stage_st(0, 0, i, v0, v1);
    }
    uint4 Ac[4];
    if (active) {
#pragma unroll
        for (int q = 0; q < 4; ++q)
            Ac[q] = wf4[(q >> 1) * 256 + (wm * 2 + (q & 1)) * 32 + lane];
    }
    __syncthreads();

    for (int chunk = 0; chunk < 8; ++chunk) {
        const int hb = chunk & 1;
        const uint32_t hoff = (uint32_t)hb * 16320u;
        for (int tap = 0; tap < 9; ++tap) {
            const int cid = chunk * 9 + tap;

            // ---- staging LOAD phase: issue global loads early ----
            float s0a = 0.f, s1a = 0.f, s0b = 0.f, s1b = 0.f;
            int i0 = -1, i1 = -1;
            if (chunk < 7) {
                int lo = tap * 368;
                int hi = lo + 368; if (hi > 3264) hi = 3264;
                int ia = lo + tid;
                if (ia < hi) { i0 = ia; stage_ld(chunk + 1, ia, s0a, s1a); }
                if (THREADS < 368) {
                    int ib = ia + THREADS;
                    if (ib < hi) { i1 = ib; stage_ld(chunk + 1, ib, s0b, s1b); }
                }
            }
            // ---- A prefetch for next tap ----
            uint4 An[4];
            if (active && cid < 71) {
                const uint4* wf = wf4 + (long)(cid + 1) * 512;
#pragma unroll
                for (int q = 0; q < 4; ++q)
                    An[q] = wf[(q >> 1) * 256 + (wm * 2 + (q & 1)) * 32 + lane];
            }
            // ---- MMA block (latency-hiding window) ----
            if (active) {
                const uint32_t toff = hoff + (uint32_t)(((tap / 3) * 34 + (tap % 3)) * 80);
#pragma unroll
                for (int ks = 0; ks < 2; ++ks) {
                    const uint32_t o2 = toff + ks * 32;
#pragma unroll
                    for (int p = 0; p < 4; ++p) {
                        uint32_t b[4];
                        ldsm4(b, bAddr[p] + o2);
                        mma16(acc[0][2 * p],     (const uint32_t*)&Ac[ks * 2],     b[0], b[1]);
                        mma16(acc[1][2 * p],     (const uint32_t*)&Ac[ks * 2 + 1], b[0], b[1]);
                        mma16(acc[0][2 * p + 1], (const uint32_t*)&Ac[ks * 2],     b[2], b[3]);
                        mma16(acc[1][2 * p + 1], (const uint32_t*)&Ac[ks * 2 + 1], b[2], b[3]);
                    }
                }
            }
            // ---- staging STORE phase: data arrived during MMAs ----
            if (i0 >= 0) stage_st(chunk + 1, hb ^ 1, i0, s0a, s1a);
            if (THREADS < 368 && i1 >= 0) stage_st(chunk + 1, hb ^ 1, i1, s0b, s1b);
            if (active && cid < 71) {
                Ac[0] = An[0]; Ac[1] = An[1]; Ac[2] = An[2]; Ac[3] = An[3];
            }
        }
        __syncthreads();
    }

    if (!active) return;

    // ---- epilogue ----
#pragma unroll
    for (int mbi = 0; mbi < 2; ++mbi) {
        const int ocl = (wm * 2 + mbi) * 16 + g;
        const int oc = ocBase + ocl;
        if (STAGE < 2) {
            float* outBase = (tower ? out_reg : out_cls) + SOFF[l];
            const float* bias = tower ? b_reg : b_cls;
            const float bv0 = bias[oc], bv1 = bias[oc + 8];
            float* o0 = outBase + ((long)n * 256 + oc) * HW;
#pragma unroll
            for (int nb = 0; nb < 8; ++nb) {
                int pxl = wn * 64 + nb * 8 + 2 * t;
                int ygl = y0 + (pxl >> 5);
                if (ygl >= H) continue;
                long idx = (long)ygl * W + x0 + (pxl & 31);
                *(float2*)(o0 + idx) =
                    make_float2(acc[mbi][nb][0] + bv0, acc[mbi][nb][1] + bv0);
                *(float2*)(o0 + 8L * HW + idx) =
                    make_float2(acc[mbi][nb][2] + bv1, acc[mbi][nb][3] + bv1);
            }
        } else if (tower == 0) {   // cls head
            float* out = out_cls;
#pragma unroll
            for (int nb = 0; nb < 8; ++nb) {
                int pxl = wn * 64 + nb * 8 + 2 * t;
                int ygl = y0 + (pxl >> 5);
                if (ygl >= H) continue;
                int pxg = ygl * W + x0 + (pxl & 31);
                long b = ((long)n * NPIX + OOFF[l] + pxg) * 20;
                if (oc < 20) {
                    float bv = b_cls[oc];
                    out[b + oc]      = acc[mbi][nb][0] + bv;
                    out[b + 20 + oc] = acc[mbi][nb][1] + bv;
                }
                if (oc + 8 < 20) {
                    float bv = b_cls[oc + 8];
                    out[b + oc + 8]      = acc[mbi][nb][2] + bv;
                    out[b + 20 + oc + 8] = acc[mbi][nb][3] + bv;
                }
            }
        } else {                   // reg + ctr head
            float* out = out_reg;
#pragma unroll
            for (int nb = 0; nb < 8; ++nb) {
                int pxl = wn * 64 + nb * 8 + 2 * t;
                int ygl = y0 + (pxl >> 5);
                if (ygl >= H) continue;
                int pxg = ygl * W + x0 + (pxl & 31);
#pragma unroll
                for (int rrj = 0; rrj < 2; ++rrj) {
                    int ocr = oc + rrj * 8;
                    float v0 = acc[mbi][nb][rrj * 2 + 0];
                    float v1 = acc[mbi][nb][rrj * 2 + 1];
                    if (ocr < 4) {
                        float bv = b_reg[ocr];
                        long rb = REG_BASE + (long)n * 67200 + (long)(OOFF[l] + pxg) * 4 + ocr;
                        out[rb]     = fmaxf(v0 + bv, 0.f);
                        out[rb + 4] = fmaxf(v1 + bv, 0.f);
                    } else if (ocr == 4) {
                        float bv = b_ctr[0];
                        long cb = CTR_BASE + (long)n * NPIX + OOFF[l] + pxg;
                        out[cb]     = v0 + bv;
                        out[cb + 1] = v1 + bv;
                    }
                }
            }
        }
    }
}

// ---------------------------------------------------------------------------
// Weight reorders -> fragment-linear half2 (unchanged layout).
// ---------------------------------------------------------------------------
__device__ __forceinline__ void frag_decode(int d, int& r, int& chunk, int& tap,
                                            int& oc128, int& icp)
{
    int j = d & 3; int q = d >> 2;
    int lane = q & 31; q >>= 5;
    int mb = q & 7;  q >>= 3;
    int ks = q & 1;  q >>= 1;
    tap = q % 9; q /= 9;
    chunk = q & 7; q >>= 3;
    r = q;
    oc128 = mb * 16 + (lane >> 2) + (j & 1) * 8;
    icp   = chunk * 32 + ks * 16 + (lane & 3) * 2 + ((j >> 1) & 1) * 8;
}

__global__ void reorder_tower(const float* __restrict__ w, uint32_t* __restrict__ dst)
{
    int d = blockIdx.x * 256 + threadIdx.x;
    if (d >= 589824) return;
    int r, chunk, tap, oc128, icp;
    frag_decode(d, r, chunk, tap, oc128, icp);
    int layer = r >> 1;
    int oc = (r & 1) * 128 + oc128;
    const float* src = w + (long)layer * 589824;
    float v0 = src[((long)oc * 256 + icp) * 9 + tap];
    float v1 = src[((long)oc * 256 + icp + 1) * 9 + tap];
    __half2 h = __floats2half2_rn(v0, v1);
    dst[d] = *(uint32_t*)&h;
}

__global__ void reorder_heads(const float* __restrict__ wcls, const float* __restrict__ wreg,
                              const float* __restrict__ wctr, uint32_t* __restrict__ dst)
{
    int d = blockIdx.x * 256 + threadIdx.x;
    if (d >= 294912) return;
    int r, chunk, tap, oc128, icp;
    frag_decode(d, r, chunk, tap, oc128, icp);
    int oc = oc128;
    float v0 = 0.f, v1 = 0.f;
    if (r == 0) {
        if (oc < 20) {
            v0 = wcls[((long)oc * 256 + icp) * 9 + tap];
            v1 = wcls[((long)oc * 256 + icp + 1) * 9 + tap];
        }
    } else {
        if (oc < 4) {
            v0 = wreg[((long)oc * 256 + icp) * 9 + tap];
            v1 = wreg[((long)oc * 256 + icp + 1) * 9 + tap];
        } else if (oc == 4) {
            v0 = wctr[(long)icp * 9 + tap];
            v1 = wctr[(long)(icp + 1) * 9 + tap];
        }
    }
    __half2 h = __floats2half2_rn(v0, v1);
    dst[d] = *(uint32_t*)&h;
}

// ---------------------------------------------------------------------------
// GroupNorm stats for all (tower, level) pairs in one launch.
// ---------------------------------------------------------------------------
__global__ void gn_stats_all(const float* __restrict__ bufCls, const float* __restrict__ bufReg)
{
    const int by = blockIdx.y;
    const int tower = by / 3, l = by - tower * 3;
    const int HWs[3] = { 12800, 3200, 800 };
    const long SOFF[3] = { 0L, 26214400L, 32768000L };
    const int HW = HWs[l];
    const int n = blockIdx.x >> 4;
    const int g = blockIdx.x & 15;
    const float4* p = (const float4*)((tower ? bufReg : bufCls) + SOFF[l]
                                      + ((long)n * 256 + (long)g * 16) * HW);
    const int total4 = (16 * HW) >> 2;
    float s = 0.f, s2 = 0.f;
    for (int i = threadIdx.x; i < total4; i += blockDim.x) {
        float4 v = p[i];
        s  += v.x + v.y + v.z + v.w;
        s2 += v.x * v.x + v.y * v.y + v.z * v.z + v.w * v.w;
    }
    __shared__ float rs[8], rs2[8];
#pragma unroll
    for (int o = 16; o; o >>= 1) {
        s  += __shfl_xor_sync(~0u, s, o);
        s2 += __shfl_xor_sync(~0u, s2, o);
    }
    const int w = threadIdx.x >> 5, lid = threadIdx.x & 31;
    if (lid == 0) { rs[w] = s; rs2[w] = s2; }
    __syncthreads();
    if (w == 0) {
        s  = (lid < 8) ? rs[lid]  : 0.f;
        s2 = (lid < 8) ? rs2[lid] : 0.f;
#pragma unroll
        for (int o = 4; o; o >>= 1) {
            s  += __shfl_xor_sync(~0u, s, o);
            s2 += __shfl_xor_sync(~0u, s2, o);
        }
        if (lid == 0) {
            float inv = 1.f / (float)(16 * HW);
            float m = s * inv;
            g_mean[by * 128 + blockIdx.x] = m;
            g_rstd[by * 128 + blockIdx.x] = rsqrtf(s2 * inv - m * m + 1e-5f);
        }
    }
}

// ---------------------------------------------------------------------------
extern "C" void kernel_launch(void* const* d_in, const int* in_sizes, int n_in,
                              void* d_out, int out_size)
{
    (void)in_sizes; (void)n_in; (void)out_size;
    const float* feat0 = (const float*)d_in[0];
    const float* feat1 = (const float*)d_in[1];
    const float* feat2 = (const float*)d_in[2];
    const float* cls_conv_w = (const float*)d_in[3];
    const float* cls_conv_b = (const float*)d_in[4];
    const float* cls_gn_g = (const float*)d_in[5];
    const float* cls_gn_b = (const float*)d_in[6];
    const float* cls_out_w = (const float*)d_in[7];
    const float* cls_out_b = (const float*)d_in[8];
    const float* reg_conv_w = (const float*)d_in[9];
    const float* reg_conv_b = (const float*)d_in[10];
    const float* reg_gn_g = (const float*)d_in[11];
    const float* reg_gn_b = (const float*)d_in[12];
    const float* reg_out_w = (const float*)d_in[13];
    const float* reg_out_b = (const float*)d_in[14];
    const float* ctr_w = (const float*)d_in[15];
    const float* ctr_b = (const float*)d_in[16];
    float* out = (float*)d_out;

    float *pA, *pB, *pC, *pD;
    uint32_t* pW;
    cudaGetSymbolAddress((void**)&pA, g_A);
    cudaGetSymbolAddress((void**)&pB, g_B);
    cudaGetSymbolAddress((void**)&pC, g_C);
    cudaGetSymbolAddress((void**)&pD, g_D);
    cudaGetSymbolAddress((void**)&pW, g_W);

    // weight reorders
    reorder_tower<<<2304, 256>>>(cls_conv_w, pW);
    reorder_tower<<<2304, 256>>>(reg_conv_w, pW + 589824);
    reorder_heads<<<1152, 256>>>(cls_out_w, reg_out_w, ctr_w, pW + 1179648);

    // stage 1: conv1 (both towers, all levels; 512-thread CTAs, both oc tiles)
    conv_mma<0, 16><<<dim3(133, 2, 8), 512>>>(feat0, feat1, feat2, pW,
                                              cls_conv_b, reg_conv_b, nullptr,
                                              nullptr, nullptr, nullptr, nullptr,
                                              pA, pC);
    gn_stats_all<<<dim3(128, 6), 256>>>(pA, pC);

    // stage 2: conv2 (GN layer0 fused)
    conv_mma<1, 16><<<dim3(133, 2, 8), 512>>>(pA, pC, nullptr, pW,
                                              cls_conv_b + 256, reg_conv_b + 256, nullptr,
                                              cls_gn_g, cls_gn_b, reg_gn_g, reg_gn_b,
                                              pB, pD);
    gn_stats_all<<<dim3(128, 6), 256>>>(pB, pD);

    // stage 3: heads (GN layer1 fused; 256-thread CTAs)
    conv_mma<2, 8><<<dim3(133, 2, 8), 256>>>(pB, pD, nullptr, pW,
                                             cls_out_b, reg_out_b, ctr_b,
                                             cls_gn_g + 256, cls_gn_b + 256,
                                             reg_gn_g + 256, reg_gn_b + 256,
                                             out, out);
}